// round 6
// baseline (speedup 1.0000x reference)
#include <cuda_runtime.h>
#include <math.h>

#define BB 1024
#define TT 200
#define EE 64

// ---------------- scratch (__device__ globals: allocation-free) ----------------
__device__ float g_S1[(size_t)BB * TT * 256];   // LAU layer-1 sigmoid outputs
__device__ float g_X [BB * 448];
__device__ float g_Z1[BB * 512];
__device__ float g_Z2[BB * 256];
__device__ float g_sc0[448], g_sh0[448];
__device__ float g_sc1[512], g_sh1[512];
__device__ float g_sc2[256], g_sh2[256];

__device__ __forceinline__ float sigm(float x) { return 1.0f / (1.0f + __expf(-x)); }

// =====================================================================
// K1: per-b -- build Weff/c1, gather hist, GEMM1 (200x128 @ 128x256),
//     sigmoid -> g_S1
// =====================================================================
struct SmemK1 {
    float sWe[128 * 256];   // 128KB  Weff[b] = W1b - W1c + diag(cur)*W1d
    float hbuf[64 * 128];   // 32KB   history row tile
    float c1s[256];         // c1[b] = b1 + cur @ (W1a + W1c)
    float curs[128];
    int   hm[TT];
    int   hc[TT];
};

__global__ void __launch_bounds__(256) k1_kernel(
    const int* __restrict__ mid, const int* __restrict__ catid,
    const int* __restrict__ hmid, const int* __restrict__ hcat,
    const float* __restrict__ mat_table, const float* __restrict__ cat_table,
    const float* __restrict__ w1, const float* __restrict__ b1)
{
    extern __shared__ __align__(16) char smem_raw[];
    SmemK1& s = *reinterpret_cast<SmemK1*>(smem_raw);
    const int b = blockIdx.x, tid = threadIdx.x;

    if (tid < 128) {
        s.curs[tid] = (tid < 64) ? mat_table[(size_t)mid[b] * EE + tid]
                                 : cat_table[(size_t)catid[b] * EE + (tid - 64)];
    }
    for (int i = tid; i < TT; i += 256) {
        s.hm[i] = hmid[b * TT + i];
        s.hc[i] = hcat[b * TT + i];
    }
    __syncthreads();

    {   // c1[j] = b1[j] + sum_k cur[k] * (W1[k][j] + W1[256+k][j])
        const int j = tid;
        float acc = b1[j];
#pragma unroll 8
        for (int k = 0; k < 128; k++)
            acc += s.curs[k] * (w1[k * 256 + j] + w1[(256 + k) * 256 + j]);
        s.c1s[j] = acc;
    }
    // Weff[k][j] = W1[128+k][j] - W1[256+k][j] + cur[k]*W1[384+k][j]
    for (int idx = tid; idx < 128 * 256; idx += 256) {
        int k = idx >> 8;
        s.sWe[idx] = w1[(128 + k) * 256 + (idx & 255)]
                   - w1[(256 + k) * 256 + (idx & 255)]
                   + s.curs[k] * w1[(384 + k) * 256 + (idx & 255)];
    }
    __syncthreads();

    const int w = tid >> 5, lane = tid & 31;
    const int r0 = (w >> 1) * 16;
    const int c0 = (w & 1) * 128 + lane * 4;
    const float4* hb4 = reinterpret_cast<const float4*>(s.hbuf);

    for (int rt0 = 0; rt0 < TT; rt0 += 64) {
        int nr = min(64, TT - rt0);
        // gather 64x128 history tile (zero-pad invalid rows)
        for (int i = tid; i < 64 * 32; i += 256) {
            int r = i >> 5, q = i & 31;
            float4 v = make_float4(0.f, 0.f, 0.f, 0.f);
            if (r < nr) {
                int t = rt0 + r;
                const float* src = (q < 16)
                    ? (mat_table + (size_t)s.hm[t] * EE + q * 4)
                    : (cat_table + (size_t)s.hc[t] * EE + (q - 16) * 4);
                v = *reinterpret_cast<const float4*>(src);
            }
            reinterpret_cast<float4*>(s.hbuf)[i] = v;
        }
        __syncthreads();

        float acc[16][4];
#pragma unroll
        for (int i = 0; i < 16; i++) {
            acc[i][0] = 0.f; acc[i][1] = 0.f; acc[i][2] = 0.f; acc[i][3] = 0.f;
        }

#pragma unroll 1
        for (int k4 = 0; k4 < 32; k4++) {
            float4 bv0 = *reinterpret_cast<const float4*>(&s.sWe[(k4 * 4 + 0) * 256 + c0]);
            float4 bv1 = *reinterpret_cast<const float4*>(&s.sWe[(k4 * 4 + 1) * 256 + c0]);
            float4 bv2 = *reinterpret_cast<const float4*>(&s.sWe[(k4 * 4 + 2) * 256 + c0]);
            float4 bv3 = *reinterpret_cast<const float4*>(&s.sWe[(k4 * 4 + 3) * 256 + c0]);
#pragma unroll
            for (int i = 0; i < 16; i++) {
                float4 av = hb4[(r0 + i) * 32 + k4];   // warp-broadcast
                acc[i][0] += av.x * bv0.x; acc[i][1] += av.x * bv0.y;
                acc[i][2] += av.x * bv0.z; acc[i][3] += av.x * bv0.w;
                acc[i][0] += av.y * bv1.x; acc[i][1] += av.y * bv1.y;
                acc[i][2] += av.y * bv1.z; acc[i][3] += av.y * bv1.w;
                acc[i][0] += av.z * bv2.x; acc[i][1] += av.z * bv2.y;
                acc[i][2] += av.z * bv2.z; acc[i][3] += av.z * bv2.w;
                acc[i][0] += av.w * bv3.x; acc[i][1] += av.w * bv3.y;
                acc[i][2] += av.w * bv3.z; acc[i][3] += av.w * bv3.w;
            }
        }
#pragma unroll
        for (int i = 0; i < 16; i++) {
            int t = rt0 + r0 + i;
            if (t < TT) {
                float4 o;
                o.x = sigm(acc[i][0] + s.c1s[c0 + 0]);
                o.y = sigm(acc[i][1] + s.c1s[c0 + 1]);
                o.z = sigm(acc[i][2] + s.c1s[c0 + 2]);
                o.w = sigm(acc[i][3] + s.c1s[c0 + 3]);
                *reinterpret_cast<float4*>(&g_S1[((size_t)b * TT + t) * 256 + c0]) = o;
            }
        }
        __syncthreads();
    }
}

// =====================================================================
// K2: per-b -- GEMM2 (200x256 @ 256x128) + sigmoid + dot(w3) -> aw,
//     masked softmax, lau & masked-mean via regather, write X[b][448]
// =====================================================================
struct SmemK2 {
    float sW2[256 * 128];   // 128KB
    float s1t[64 * 256];    // 64KB S1 row tile
    float aw[TT];
    float curs[128];
    float lau[128];
    float hsum[128];
    float w3s[128];
    float b2s[128];
    float red[32];
    float maxv, sumv, cntv;
    int   hm[TT], hc[TT], mk[TT];
};

__global__ void __launch_bounds__(256) k2_kernel(
    const int* __restrict__ uid, const int* __restrict__ mid,
    const int* __restrict__ catid,
    const int* __restrict__ hmid, const int* __restrict__ hcat,
    const int* __restrict__ mask,
    const float* __restrict__ user_table, const float* __restrict__ mat_table,
    const float* __restrict__ cat_table,
    const float* __restrict__ w2, const float* __restrict__ b2,
    const float* __restrict__ w3, const float* __restrict__ b3)
{
    extern __shared__ __align__(16) char smem_raw[];
    SmemK2& s = *reinterpret_cast<SmemK2*>(smem_raw);
    const int b = blockIdx.x, tid = threadIdx.x;
    const int w = tid >> 5, lane = tid & 31;

    for (int i = tid; i < (256 * 128) / 4; i += 256)
        reinterpret_cast<float4*>(s.sW2)[i] = reinterpret_cast<const float4*>(w2)[i];
    if (tid < 128) {
        s.w3s[tid] = w3[tid];
        s.b2s[tid] = b2[tid];
        s.lau[tid]  = 0.f;
        s.hsum[tid] = 0.f;
        s.curs[tid] = (tid < 64) ? mat_table[(size_t)mid[b] * EE + tid]
                                 : cat_table[(size_t)catid[b] * EE + (tid - 64)];
    }
    float b3v = b3[0];
    for (int i = tid; i < TT; i += 256) {
        s.hm[i] = hmid[b * TT + i];
        s.hc[i] = hcat[b * TT + i];
        s.mk[i] = mask[b * TT + i];
        s.aw[i] = b3v;
    }
    __syncthreads();

    const int r0 = (w >> 1) * 16;
    const int c0 = (w & 1) * 64 + lane * 2;

    for (int rt0 = 0; rt0 < TT; rt0 += 64) {
        int nr = min(64, TT - rt0);
        for (int i = tid; i < 64 * 64; i += 256) {   // 64 rows x 64 float4
            int r = i >> 6, q = i & 63;
            float4 v = make_float4(0.f, 0.f, 0.f, 0.f);
            if (r < nr)
                v = *reinterpret_cast<const float4*>(
                        &g_S1[((size_t)b * TT + rt0 + r) * 256 + q * 4]);
            reinterpret_cast<float4*>(s.s1t)[i] = v;
        }
        __syncthreads();

        float acc[16][2];
#pragma unroll
        for (int i = 0; i < 16; i++) { acc[i][0] = 0.f; acc[i][1] = 0.f; }

#pragma unroll 1
        for (int k = 0; k < 256; k += 4) {
            float2 b0 = *reinterpret_cast<const float2*>(&s.sW2[(k + 0) * 128 + c0]);
            float2 b1v = *reinterpret_cast<const float2*>(&s.sW2[(k + 1) * 128 + c0]);
            float2 b2v = *reinterpret_cast<const float2*>(&s.sW2[(k + 2) * 128 + c0]);
            float2 b3q = *reinterpret_cast<const float2*>(&s.sW2[(k + 3) * 128 + c0]);
#pragma unroll
            for (int i = 0; i < 16; i++) {
                float4 av = *reinterpret_cast<const float4*>(&s.s1t[(r0 + i) * 256 + k]);
                acc[i][0] += av.x * b0.x;  acc[i][1] += av.x * b0.y;
                acc[i][0] += av.y * b1v.x; acc[i][1] += av.y * b1v.y;
                acc[i][0] += av.z * b2v.x; acc[i][1] += av.z * b2v.y;
                acc[i][0] += av.w * b3q.x; acc[i][1] += av.w * b3q.y;
            }
        }
        // sigmoid + dot with w3, reduce across the 64 lanes covering 128 cols
#pragma unroll
        for (int i = 0; i < 16; i++) {
            float p = sigm(acc[i][0] + s.b2s[c0]) * s.w3s[c0]
                    + sigm(acc[i][1] + s.b2s[c0 + 1]) * s.w3s[c0 + 1];
#pragma unroll
            for (int o = 16; o > 0; o >>= 1)
                p += __shfl_xor_sync(0xffffffffu, p, o);
            int t = rt0 + r0 + i;
            if (lane == 0 && t < TT) atomicAdd(&s.aw[t], p);
        }
        __syncthreads();
    }

    // ---------------- masked softmax over t ----------------
    {
        float v = -3.0e38f;
        if (tid < TT && s.mk[tid]) v = s.aw[tid];
#pragma unroll
        for (int o = 16; o > 0; o >>= 1)
            v = fmaxf(v, __shfl_xor_sync(0xffffffffu, v, o));
        if (lane == 0) s.red[w] = v;
        __syncthreads();
        if (tid == 0) {
            float m = s.red[0];
            for (int i = 1; i < 8; i++) m = fmaxf(m, s.red[i]);
            s.maxv = m;
        }
        __syncthreads();

        float e = 0.f, cf = 0.f;
        if (tid < TT && s.mk[tid]) { e = __expf(s.aw[tid] - s.maxv); cf = 1.f; }
        float se = e, scf = cf;
#pragma unroll
        for (int o = 16; o > 0; o >>= 1) {
            se  += __shfl_xor_sync(0xffffffffu, se, o);
            scf += __shfl_xor_sync(0xffffffffu, scf, o);
        }
        if (lane == 0) { s.red[w] = se; s.red[16 + w] = scf; }
        __syncthreads();
        if (tid == 0) {
            float ss = 0.f, cc = 0.f;
            for (int i = 0; i < 8; i++) { ss += s.red[i]; cc += s.red[16 + i]; }
            s.sumv = ss; s.cntv = cc;
        }
        __syncthreads();
        if (tid < TT) s.aw[tid] = e / s.sumv;   // scores (mask already applied)
        __syncthreads();
    }

    // ---------------- lau + masked sum over history ----------------
    {
        int col = tid & 127, half = tid >> 7;
        float al = 0.f, ah = 0.f;
        const float* tab = (col < 64) ? mat_table : cat_table;
        int coff = (col < 64) ? col : (col - 64);
        for (int t = half; t < TT; t += 2) {
            int row = (col < 64) ? s.hm[t] : s.hc[t];
            float h = tab[(size_t)row * EE + coff];
            al += s.aw[t] * h;
            ah += (float)s.mk[t] * h;
        }
        atomicAdd(&s.lau[col], al);
        atomicAdd(&s.hsum[col], ah);
    }
    __syncthreads();

    // ---------------- write X row: [u(64), cur(128), lau(128), hmean(128)] ----
    {
        float inv = 1.0f / s.cntv;
        int ub = uid[b];
        for (int i = tid; i < 448; i += 256) {
            float v;
            if (i < 64)       v = user_table[(size_t)ub * EE + i];
            else if (i < 192) v = s.curs[i - 64];
            else if (i < 320) v = s.lau[i - 192];
            else              v = s.hsum[i - 320] * inv;
            g_X[b * 448 + i] = v;
        }
    }
}

// =====================================================================
// stats: per-column mean/var over 1024 rows -> sc/sh affine
// =====================================================================
__global__ void __launch_bounds__(256) stats_kernel(
    const float* __restrict__ Z, int rows, int cols,
    const float* __restrict__ g, const float* __restrict__ bta,
    float* __restrict__ sc, float* __restrict__ sh)
{
    int tx = threadIdx.x & 31, ty = threadIdx.x >> 5;   // 8 row-groups x 32 cols
    int col = blockIdx.x * 32 + tx;
    float su = 0.f, sq = 0.f;
    for (int r = ty; r < rows; r += 8) {
        float v = Z[(size_t)r * cols + col];
        su += v; sq += v * v;
    }
    __shared__ float ss[8][32], sqq[8][32];
    ss[ty][tx] = su; sqq[ty][tx] = sq;
    __syncthreads();
    if (ty == 0) {
        for (int i = 1; i < 8; i++) { su += ss[i][tx]; sq += sqq[i][tx]; }
        float inv = 1.0f / (float)rows;
        float mu = su * inv;
        float var = sq * inv - mu * mu;
        float scv = g[col] * rsqrtf(var + 1e-5f);
        sc[col] = scv;
        sh[col] = bta[col] - mu * scv;
    }
}

// =====================================================================
// gemm_bn: C[1024xN] = f(A) @ W + bias, f(a) = affine (+optional leaky)
// 64x64 tile per block, 256 threads, 4x4 per thread
// =====================================================================
__global__ void __launch_bounds__(256) gemm_bn(
    const float* __restrict__ A, const float* __restrict__ W,
    const float* __restrict__ bias, const float* __restrict__ sc,
    const float* __restrict__ sh, int leaky, int K, int N,
    float* __restrict__ C)
{
    __shared__ __align__(16) float Ast[32 * 68];
    __shared__ __align__(16) float Bs[32 * 64];
    int tid = threadIdx.x;
    int row0 = blockIdx.y * 64, col0 = blockIdx.x * 64;
    int ty = tid >> 4, tx = tid & 15;
    float acc[4][4];
#pragma unroll
    for (int i = 0; i < 4; i++)
        for (int j = 0; j < 4; j++) acc[i][j] = 0.f;

    for (int k0 = 0; k0 < K; k0 += 32) {
        for (int i = tid; i < 2048; i += 256) {
            int kk = i & 31, r = i >> 5;
            int k = k0 + kk;
            float v = A[(size_t)(row0 + r) * K + k];
            v = v * sc[k] + sh[k];
            if (leaky) v = (v > 0.f) ? v : 0.1f * v;
            Ast[kk * 68 + r] = v;
        }
        for (int i = tid; i < 512; i += 256) {
            int kk = i >> 4, c4 = i & 15;
            *reinterpret_cast<float4*>(&Bs[kk * 64 + c4 * 4]) =
                *reinterpret_cast<const float4*>(&W[(size_t)(k0 + kk) * N + col0 + c4 * 4]);
        }
        __syncthreads();
#pragma unroll 8
        for (int kk = 0; kk < 32; kk++) {
            float4 a = *reinterpret_cast<const float4*>(&Ast[kk * 68 + ty * 4]);
            float4 bb = *reinterpret_cast<const float4*>(&Bs[kk * 64 + tx * 4]);
            acc[0][0] += a.x * bb.x; acc[0][1] += a.x * bb.y;
            acc[0][2] += a.x * bb.z; acc[0][3] += a.x * bb.w;
            acc[1][0] += a.y * bb.x; acc[1][1] += a.y * bb.y;
            acc[1][2] += a.y * bb.z; acc[1][3] += a.y * bb.w;
            acc[2][0] += a.z * bb.x; acc[2][1] += a.z * bb.y;
            acc[2][2] += a.z * bb.z; acc[2][3] += a.z * bb.w;
            acc[3][0] += a.w * bb.x; acc[3][1] += a.w * bb.y;
            acc[3][2] += a.w * bb.z; acc[3][3] += a.w * bb.w;
        }
        __syncthreads();
    }
#pragma unroll
    for (int i = 0; i < 4; i++) {
        int r = row0 + ty * 4 + i, c = col0 + tx * 4;
        float4 o;
        o.x = acc[i][0] + bias[c + 0];
        o.y = acc[i][1] + bias[c + 1];
        o.z = acc[i][2] + bias[c + 2];
        o.w = acc[i][3] + bias[c + 3];
        *reinterpret_cast<float4*>(&C[(size_t)r * N + c]) = o;
    }
}

// =====================================================================
// final: out[b][0..1] = leaky(bn2(Z2)) @ w3 + b3
// =====================================================================
__global__ void __launch_bounds__(256) final_kernel(
    const float* __restrict__ w3, const float* __restrict__ b3,
    float* __restrict__ out)
{
    int b = blockIdx.x, tid = threadIdx.x;
    int lane = tid & 31, w = tid >> 5;
    float v = g_Z2[b * 256 + tid] * g_sc2[tid] + g_sh2[tid];
    v = (v > 0.f) ? v : 0.1f * v;
    float a0 = v * w3[tid * 2 + 0];
    float a1 = v * w3[tid * 2 + 1];
#pragma unroll
    for (int o = 16; o > 0; o >>= 1) {
        a0 += __shfl_xor_sync(0xffffffffu, a0, o);
        a1 += __shfl_xor_sync(0xffffffffu, a1, o);
    }
    __shared__ float r0s[8], r1s[8];
    if (lane == 0) { r0s[w] = a0; r1s[w] = a1; }
    __syncthreads();
    if (tid == 0) {
        float s0 = 0.f, s1 = 0.f;
        for (int i = 0; i < 8; i++) { s0 += r0s[i]; s1 += r1s[i]; }
        out[b * 2 + 0] = s0 + b3[0];
        out[b * 2 + 1] = s1 + b3[1];
    }
}

// =====================================================================
extern "C" void kernel_launch(void* const* d_in, const int* in_sizes, int n_in,
                              void* d_out, int out_size)
{
    (void)in_sizes; (void)n_in; (void)out_size;
    const int*   uid   = (const int*)d_in[0];
    const int*   mid   = (const int*)d_in[1];
    const int*   cat   = (const int*)d_in[2];
    const int*   hmid  = (const int*)d_in[3];
    const int*   hcat  = (const int*)d_in[4];
    const int*   mask  = (const int*)d_in[5];
    const float* utab  = (const float*)d_in[6];
    const float* mtab  = (const float*)d_in[7];
    const float* ctab  = (const float*)d_in[8];
    const float* lw1   = (const float*)d_in[9];
    const float* lb1   = (const float*)d_in[10];
    const float* lw2   = (const float*)d_in[11];
    const float* lb2   = (const float*)d_in[12];
    const float* lw3   = (const float*)d_in[13];
    const float* lb3   = (const float*)d_in[14];
    const float* bn0g  = (const float*)d_in[15];
    const float* bn0b  = (const float*)d_in[16];
    const float* mw1   = (const float*)d_in[17];
    const float* mb1   = (const float*)d_in[18];
    const float* bn1g  = (const float*)d_in[19];
    const float* bn1b  = (const float*)d_in[20];
    const float* mw2   = (const float*)d_in[21];
    const float* mb2   = (const float*)d_in[22];
    const float* bn2g  = (const float*)d_in[23];
    const float* bn2b  = (const float*)d_in[24];
    const float* mw3   = (const float*)d_in[25];
    const float* mb3   = (const float*)d_in[26];
    float* out = (float*)d_out;

    static int attr_done = 0;
    if (!attr_done) {
        cudaFuncSetAttribute(k1_kernel, cudaFuncAttributeMaxDynamicSharedMemorySize,
                             (int)sizeof(SmemK1));
        cudaFuncSetAttribute(k2_kernel, cudaFuncAttributeMaxDynamicSharedMemorySize,
                             (int)sizeof(SmemK2));
        attr_done = 1;
    }

    float *sc0, *sh0, *sc1, *sh1, *sc2, *sh2, *X, *Z1, *Z2;
    cudaGetSymbolAddress((void**)&sc0, g_sc0);
    cudaGetSymbolAddress((void**)&sh0, g_sh0);
    cudaGetSymbolAddress((void**)&sc1, g_sc1);
    cudaGetSymbolAddress((void**)&sh1, g_sh1);
    cudaGetSymbolAddress((void**)&sc2, g_sc2);
    cudaGetSymbolAddress((void**)&sh2, g_sh2);
    cudaGetSymbolAddress((void**)&X,  g_X);
    cudaGetSymbolAddress((void**)&Z1, g_Z1);
    cudaGetSymbolAddress((void**)&Z2, g_Z2);

    k1_kernel<<<BB, 256, sizeof(SmemK1)>>>(mid, cat, hmid, hcat, mtab, ctab, lw1, lb1);
    k2_kernel<<<BB, 256, sizeof(SmemK2)>>>(uid, mid, cat, hmid, hcat, mask,
                                           utab, mtab, ctab, lw2, lb2, lw3, lb3);

    stats_kernel<<<448 / 32, 256>>>(X, BB, 448, bn0g, bn0b, sc0, sh0);
    gemm_bn<<<dim3(512 / 64, BB / 64), 256>>>(X, mw1, mb1, sc0, sh0, 0, 448, 512, Z1);

    stats_kernel<<<512 / 32, 256>>>(Z1, BB, 512, bn1g, bn1b, sc1, sh1);
    gemm_bn<<<dim3(256 / 64, BB / 64), 256>>>(Z1, mw2, mb2, sc1, sh1, 1, 512, 256, Z2);

    stats_kernel<<<256 / 32, 256>>>(Z2, BB, 256, bn2g, bn2b, sc2, sh2);
    final_kernel<<<BB, 256>>>(mw3, mb3, out);
}

// round 9
// speedup vs baseline: 2.2773x; 2.2773x over previous
#include <cuda_runtime.h>
#include <cuda_fp16.h>
#include <math.h>
#include <stdint.h>

#define BB 1024
#define TT 200
#define EE 64

// ---------------- scratch (__device__ globals: allocation-free) ----------------
__device__ unsigned g_S1u[(size_t)BB * TT * 128];   // S1 as half2 pairs [b][t][128]
__device__ float g_X [BB * 448];
__device__ float g_Z1[BB * 512];
__device__ float g_Z2[BB * 256];
__device__ float g_sc0[448], g_sh0[448];
__device__ float g_sc1[512], g_sh1[512];
__device__ float g_sc2[256], g_sh2[256];
// fp16 operand images, plain [n][k] row-major packed as half2 along k
__device__ unsigned g_imgBbc[16384];   // (W1b - W1c)^T  [256][64 half2]
__device__ unsigned g_imgBd [16384];   // (W1d)^T        [256][64 half2]
__device__ unsigned g_imgW2T[16384];   // W2^T           [128][128 half2]
__device__ __half g_W1ach[128 * 256];  // W1a + W1c, [k][j] fp16

__device__ __forceinline__ float sigm(float x) { return 1.0f / (1.0f + __expf(-x)); }

__device__ __forceinline__ unsigned pack2(float a, float b) {
    __half2 h = __floats2half2_rn(a, b);
    return *reinterpret_cast<unsigned*>(&h);
}
__device__ __forceinline__ unsigned hfma2u(unsigned c2, unsigned d2, unsigned b2v) {
    __half2 r = __hfma2(*reinterpret_cast<__half2*>(&c2),
                        *reinterpret_cast<__half2*>(&d2),
                        *reinterpret_cast<__half2*>(&b2v));
    return *reinterpret_cast<unsigned*>(&r);
}

// warp-level HMMA: D(16x8,f32) += A(16x16,f16 row) * B(16x8,f16 col)
__device__ __forceinline__ void mma16816(float* d, const unsigned* a,
                                         unsigned b0, unsigned b1) {
    asm volatile(
        "mma.sync.aligned.m16n8k16.row.col.f32.f16.f16.f32 "
        "{%0,%1,%2,%3}, {%4,%5,%6,%7}, {%8,%9}, {%0,%1,%2,%3};"
        : "+f"(d[0]), "+f"(d[1]), "+f"(d[2]), "+f"(d[3])
        : "r"(a[0]), "r"(a[1]), "r"(a[2]), "r"(a[3]), "r"(b0), "r"(b1));
}

// =====================================================================
// prep kernels: b-invariant fp16 operand images
// =====================================================================
__global__ void __launch_bounds__(256) prep_imgs(const float* __restrict__ w1,
                                                 const float* __restrict__ w2)
{
    int gid = blockIdx.x * 256 + threadIdx.x;
    if (gid < 16384) {
        int j = gid >> 6, kk = gid & 63, k = kk * 2;
        float bc0 = w1[(128 + k) * 256 + j] - w1[(256 + k) * 256 + j];
        float bc1 = w1[(129 + k) * 256 + j] - w1[(257 + k) * 256 + j];
        g_imgBbc[gid] = pack2(bc0, bc1);
        g_imgBd [gid] = pack2(w1[(384 + k) * 256 + j], w1[(385 + k) * 256 + j]);
    } else {
        int t = gid - 16384;
        int j = t >> 7, kk = t & 127, k = kk * 2;
        g_imgW2T[t] = pack2(w2[k * 128 + j], w2[(k + 1) * 128 + j]);
    }
}

__global__ void __launch_bounds__(256) prep_w1ac(const float* __restrict__ w1)
{
    int gid = blockIdx.x * 256 + threadIdx.x;   // 16384 half2 elems
    int k = gid >> 7, j = (gid & 127) * 2;
    float a = w1[k * 256 + j]     + w1[(256 + k) * 256 + j];
    float b = w1[k * 256 + j + 1] + w1[(256 + k) * 256 + j + 1];
    reinterpret_cast<unsigned*>(g_W1ach)[gid] = pack2(a, b);
}

// =====================================================================
// K1: per-b HMMA GEMM1 (208x128 @ 128x256) + sigmoid -> g_S1u (fp16)
// =====================================================================
#define LDA1 136   // halves; row stride 272B == 4 banks mod 32
#define LDB1 136

struct SmemK1 {
    __half A[208 * LDA1];    // 56576 B
    __half Bw[256 * LDB1];   // 69632 B
    float c1s[256];
    float curs[128];
    unsigned curs2h[64];
    int hm[TT], hc[TT];
};

__global__ void __launch_bounds__(256) k1_kernel(
    const int* __restrict__ mid, const int* __restrict__ catid,
    const int* __restrict__ hmid, const int* __restrict__ hcat,
    const float* __restrict__ mat_table, const float* __restrict__ cat_table,
    const float* __restrict__ b1)
{
    extern __shared__ __align__(16) char smem_raw[];
    SmemK1& s = *reinterpret_cast<SmemK1*>(smem_raw);
    const int b = blockIdx.x, tid = threadIdx.x;
    const int wid = tid >> 5, lane = tid & 31;
    const int g = lane >> 2, t4 = lane & 3;

    if (tid < 128)
        s.curs[tid] = (tid < 64) ? mat_table[(size_t)mid[b] * EE + tid]
                                 : cat_table[(size_t)catid[b] * EE + (tid - 64)];
    for (int i = tid; i < TT; i += 256) {
        s.hm[i] = hmid[b * TT + i];
        s.hc[i] = hcat[b * TT + i];
    }
    __syncthreads();
    if (tid < 64) s.curs2h[tid] = pack2(s.curs[2 * tid], s.curs[2 * tid + 1]);
    __syncthreads();

    {   // c1[j] = b1[j] + sum_k cur[k] * W1ac[k][j]
        const int j = tid;
        float acc = b1[j];
#pragma unroll 8
        for (int k = 0; k < 128; k++)
            acc += s.curs[k] * __half2float(g_W1ach[k * 256 + j]);
        s.c1s[j] = acc;
    }
    // B = Weff^T [256][128] fp16
    for (int t = tid; t < 16384; t += 256) {
        int j = t >> 6, kk = t & 63;
        unsigned un = hfma2u(s.curs2h[kk], g_imgBd[t], g_imgBbc[t]);
        *reinterpret_cast<unsigned*>(&s.Bw[j * LDB1 + kk * 2]) = un;
    }
    // A = hist fp16 rows 0..199
    for (int t = tid; t < 3200; t += 256) {
        int r = t >> 4, kg = t & 15;
        const float* src = (kg < 8)
            ? (mat_table + (size_t)s.hm[r] * EE + kg * 8)
            : (cat_table + (size_t)s.hc[r] * EE + (kg - 8) * 8);
        float4 f0 = *reinterpret_cast<const float4*>(src);
        float4 f1 = *reinterpret_cast<const float4*>(src + 4);
        uint4 o;
        o.x = pack2(f0.x, f0.y); o.y = pack2(f0.z, f0.w);
        o.z = pack2(f1.x, f1.y); o.w = pack2(f1.z, f1.w);
        *reinterpret_cast<uint4*>(&s.A[r * LDA1 + kg * 8]) = o;
    }
    // zero pad rows 200..207
    for (int i = tid; i < 4 * LDA1; i += 256)
        *reinterpret_cast<unsigned*>(&s.A[200 * LDA1 + 2 * i]) = 0u;
    __syncthreads();

    // 52 warp tiles: m16 x n64, K=128
    for (int tt = wid; tt < 52; tt += 8) {
        int m0 = (tt % 13) * 16, n0 = (tt / 13) * 64;
        float d[8][4];
#pragma unroll
        for (int i = 0; i < 8; i++) { d[i][0] = d[i][1] = d[i][2] = d[i][3] = 0.f; }

#pragma unroll 2
        for (int k0 = 0; k0 < 128; k0 += 16) {
            unsigned av[4];
            av[0] = *reinterpret_cast<const unsigned*>(&s.A[(m0 + g)     * LDA1 + k0 + t4 * 2]);
            av[1] = *reinterpret_cast<const unsigned*>(&s.A[(m0 + g + 8) * LDA1 + k0 + t4 * 2]);
            av[2] = *reinterpret_cast<const unsigned*>(&s.A[(m0 + g)     * LDA1 + k0 + 8 + t4 * 2]);
            av[3] = *reinterpret_cast<const unsigned*>(&s.A[(m0 + g + 8) * LDA1 + k0 + 8 + t4 * 2]);
#pragma unroll
            for (int n8 = 0; n8 < 8; n8++) {
                int nr = n0 + n8 * 8 + g;
                unsigned b0v = *reinterpret_cast<const unsigned*>(&s.Bw[nr * LDB1 + k0 + t4 * 2]);
                unsigned b1v = *reinterpret_cast<const unsigned*>(&s.Bw[nr * LDB1 + k0 + 8 + t4 * 2]);
                mma16816(d[n8], av, b0v, b1v);
            }
        }
        // epilogue: sigmoid(D + c1) -> g_S1u
        int r0 = m0 + g, r1 = m0 + g + 8;
#pragma unroll
        for (int n8 = 0; n8 < 8; n8++) {
            int col = n0 + n8 * 8 + t4 * 2;
            int j2 = col >> 1;
            g_S1u[((size_t)b * TT + r0) * 128 + j2] =
                pack2(sigm(d[n8][0] + s.c1s[col]), sigm(d[n8][1] + s.c1s[col + 1]));
            if (r1 < TT)
                g_S1u[((size_t)b * TT + r1) * 128 + j2] =
                    pack2(sigm(d[n8][2] + s.c1s[col]), sigm(d[n8][3] + s.c1s[col + 1]));
        }
    }
}

// =====================================================================
// K2: per-b HMMA GEMM2 (208x256 @ 256x128) + sigmoid + w3-dot -> aw,
//     masked softmax, lau & masked-mean, write X[b][448]
// =====================================================================
#define LDA2 264
#define LDB2 264

struct SmemK2 {
    __half A[208 * LDA2];    // 109824 B
    __half Bw[128 * LDB2];   // 67584 B
    float aw[208];
    float w3s[128], b2s[128];
    float curs[128], lau[128], hsum[128];
    float red[32];
    float maxv, sumv, cntv;
    int hm[TT], hc[TT], mk[TT];
};

__global__ void __launch_bounds__(256) k2_kernel(
    const int* __restrict__ uid, const int* __restrict__ mid,
    const int* __restrict__ catid,
    const int* __restrict__ hmid, const int* __restrict__ hcat,
    const int* __restrict__ mask,
    const float* __restrict__ user_table, const float* __restrict__ mat_table,
    const float* __restrict__ cat_table,
    const float* __restrict__ b2, const float* __restrict__ w3,
    const float* __restrict__ b3)
{
    extern __shared__ __align__(16) char smem_raw[];
    SmemK2& s = *reinterpret_cast<SmemK2*>(smem_raw);
    const int b = blockIdx.x, tid = threadIdx.x;
    const int wid = tid >> 5, lane = tid & 31;
    const int g = lane >> 2, t4 = lane & 3;

    if (tid < 128) {
        s.w3s[tid] = w3[tid];
        s.b2s[tid] = b2[tid];
        s.lau[tid]  = 0.f;
        s.hsum[tid] = 0.f;
        s.curs[tid] = (tid < 64) ? mat_table[(size_t)mid[b] * EE + tid]
                                 : cat_table[(size_t)catid[b] * EE + (tid - 64)];
    }
    float b3v = b3[0];
    for (int i = tid; i < TT; i += 256) {
        s.hm[i] = hmid[b * TT + i];
        s.hc[i] = hcat[b * TT + i];
        s.mk[i] = mask[b * TT + i];
        s.aw[i] = b3v;
    }
    // B copy
    for (int t = tid; t < 16384; t += 256) {
        int j = t >> 7, kk = t & 127;
        *reinterpret_cast<unsigned*>(&s.Bw[j * LDB2 + kk * 2]) = g_imgW2T[t];
    }
    // A copy from g_S1u rows 0..199
    for (int t = tid; t < 6400; t += 256) {
        int r = t >> 5, q = t & 31;
        uint4 v = *reinterpret_cast<const uint4*>(&g_S1u[((size_t)b * TT + r) * 128 + q * 4]);
        *reinterpret_cast<uint4*>(&s.A[r * LDA2 + q * 8]) = v;
    }
    // zero pad rows 200..207
    for (int i = tid; i < 4 * LDA2; i += 256)
        *reinterpret_cast<unsigned*>(&s.A[200 * LDA2 + 2 * i]) = 0u;
    __syncthreads();

    // 26 warp tiles: m16 x n64, K=256
    for (int tt = wid; tt < 26; tt += 8) {
        int m0 = (tt % 13) * 16, n0 = (tt / 13) * 64;
        float d[8][4];
#pragma unroll
        for (int i = 0; i < 8; i++) { d[i][0] = d[i][1] = d[i][2] = d[i][3] = 0.f; }

#pragma unroll 2
        for (int k0 = 0; k0 < 256; k0 += 16) {
            unsigned av[4];
            av[0] = *reinterpret_cast<const unsigned*>(&s.A[(m0 + g)     * LDA2 + k0 + t4 * 2]);
            av[1] = *reinterpret_cast<const unsigned*>(&s.A[(m0 + g + 8) * LDA2 + k0 + t4 * 2]);
            av[2] = *reinterpret_cast<const unsigned*>(&s.A[(m0 + g)     * LDA2 + k0 + 8 + t4 * 2]);
            av[3] = *reinterpret_cast<const unsigned*>(&s.A[(m0 + g + 8) * LDA2 + k0 + 8 + t4 * 2]);
#pragma unroll
            for (int n8 = 0; n8 < 8; n8++) {
                int nr = n0 + n8 * 8 + g;
                unsigned b0v = *reinterpret_cast<const unsigned*>(&s.Bw[nr * LDB2 + k0 + t4 * 2]);
                unsigned b1v = *reinterpret_cast<const unsigned*>(&s.Bw[nr * LDB2 + k0 + 8 + t4 * 2]);
                mma16816(d[n8], av, b0v, b1v);
            }
        }
        // epilogue: partial aw via sigmoid + w3-dot, reduce over 4 lanes/row
        float p0 = 0.f, p1 = 0.f;
#pragma unroll
        for (int n8 = 0; n8 < 8; n8++) {
            int c = n0 + n8 * 8 + t4 * 2;
            p0 += sigm(d[n8][0] + s.b2s[c]) * s.w3s[c]
                + sigm(d[n8][1] + s.b2s[c + 1]) * s.w3s[c + 1];
            p1 += sigm(d[n8][2] + s.b2s[c]) * s.w3s[c]
                + sigm(d[n8][3] + s.b2s[c + 1]) * s.w3s[c + 1];
        }
        p0 += __shfl_xor_sync(0xffffffffu, p0, 1);
        p0 += __shfl_xor_sync(0xffffffffu, p0, 2);
        p1 += __shfl_xor_sync(0xffffffffu, p1, 1);
        p1 += __shfl_xor_sync(0xffffffffu, p1, 2);
        if (t4 == 0) {
            atomicAdd(&s.aw[m0 + g], p0);
            if (m0 + g + 8 < TT) atomicAdd(&s.aw[m0 + g + 8], p1);
        }
    }
    __syncthreads();

    // ---------------- masked softmax over t ----------------
    {
        float v = -3.0e38f;
        if (tid < TT && s.mk[tid]) v = s.aw[tid];
#pragma unroll
        for (int o = 16; o > 0; o >>= 1)
            v = fmaxf(v, __shfl_xor_sync(0xffffffffu, v, o));
        if (lane == 0) s.red[wid] = v;
        __syncthreads();
        if (tid == 0) {
            float m = s.red[0];
            for (int i = 1; i < 8; i++) m = fmaxf(m, s.red[i]);
            s.maxv = m;
        }
        __syncthreads();

        float e = 0.f, cf = 0.f;
        if (tid < TT && s.mk[tid]) { e = __expf(s.aw[tid] - s.maxv); cf = 1.f; }
        float se = e, scf = cf;
#pragma unroll
        for (int o = 16; o > 0; o >>= 1) {
            se  += __shfl_xor_sync(0xffffffffu, se, o);
            scf += __shfl_xor_sync(0xffffffffu, scf, o);
        }
        if (lane == 0) { s.red[wid] = se; s.red[16 + wid] = scf; }
        __syncthreads();
        if (tid == 0) {
            float ss = 0.f, cc = 0.f;
            for (int i = 0; i < 8; i++) { ss += s.red[i]; cc += s.red[16 + i]; }
            s.sumv = ss; s.cntv = cc;
        }
        __syncthreads();
        if (tid < TT) s.aw[tid] = e / s.sumv;
        __syncthreads();
    }

    // ---------------- lau + masked sum over history ----------------
    {
        int col = tid & 127, half = tid >> 7;
        float al = 0.f, ah = 0.f;
        const float* tab = (col < 64) ? mat_table : cat_table;
        int coff = (col < 64) ? col : (col - 64);
        for (int t2 = half; t2 < TT; t2 += 2) {
            int row = (col < 64) ? s.hm[t2] : s.hc[t2];
            float h = tab[(size_t)row * EE + coff];
            al += s.aw[t2] * h;
            ah += (float)s.mk[t2] * h;
        }
        atomicAdd(&s.lau[col], al);
        atomicAdd(&s.hsum[col], ah);
    }
    __syncthreads();

    // ---------------- write X row: [u(64), cur(128), lau(128), hmean(128)] ----
    {
        float inv = 1.0f / s.cntv;
        int ub = uid[b];
        for (int i = tid; i < 448; i += 256) {
            float v;
            if (i < 64)       v = user_table[(size_t)ub * EE + i];
            else if (i < 192) v = s.curs[i - 64];
            else if (i < 320) v = s.lau[i - 192];
            else              v = s.hsum[i - 320] * inv;
            g_X[b * 448 + i] = v;
        }
    }
}

// =====================================================================
// stats: per-column mean/var over 1024 rows -> sc/sh affine
// =====================================================================
__global__ void __launch_bounds__(256) stats_kernel(
    const float* __restrict__ Z, int rows, int cols,
    const float* __restrict__ g, const float* __restrict__ bta,
    float* __restrict__ sc, float* __restrict__ sh)
{
    int tx = threadIdx.x & 31, ty = threadIdx.x >> 5;
    int col = blockIdx.x * 32 + tx;
    float su = 0.f, sq = 0.f;
    for (int r = ty; r < rows; r += 8) {
        float v = Z[(size_t)r * cols + col];
        su += v; sq += v * v;
    }
    __shared__ float ss[8][32], sqq[8][32];
    ss[ty][tx] = su; sqq[ty][tx] = sq;
    __syncthreads();
    if (ty == 0) {
        for (int i = 1; i < 8; i++) { su += ss[i][tx]; sq += sqq[i][tx]; }
        float inv = 1.0f / (float)rows;
        float mu = su * inv;
        float var = sq * inv - mu * mu;
        float scv = g[col] * rsqrtf(var + 1e-5f);
        sc[col] = scv;
        sh[col] = bta[col] - mu * scv;
    }
}

// =====================================================================
// gemm_bn: C[1024xN] = f(A) @ W + bias, f = affine (+optional leaky)
// =====================================================================
__global__ void __launch_bounds__(256) gemm_bn(
    const float* __restrict__ A, const float* __restrict__ W,
    const float* __restrict__ bias, const float* __restrict__ sc,
    const float* __restrict__ sh, int leaky, int K, int N,
    float* __restrict__ C)
{
    __shared__ __align__(16) float Ast[32 * 68];
    __shared__ __align__(16) float Bs[32 * 64];
    int tid = threadIdx.x;
    int row0 = blockIdx.y * 64, col0 = blockIdx.x * 64;
    int ty = tid >> 4, tx = tid & 15;
    float acc[4][4];
#pragma unroll
    for (int i = 0; i < 4; i++)
        for (int j = 0; j < 4; j++) acc[i][j] = 0.f;

    for (int k0 = 0; k0 < K; k0 += 32) {
        for (int i = tid; i < 2048; i += 256) {
            int kk = i & 31, r = i >> 5;
            int k = k0 + kk;
            float v = A[(size_t)(row0 + r) * K + k];
            v = v * sc[k] + sh[k];
            if (leaky) v = (v > 0.f) ? v : 0.1f * v;
            Ast[kk * 68 + r] = v;
        }
        for (int i = tid; i < 512; i += 256) {
            int kk = i >> 4, c4 = i & 15;
            *reinterpret_cast<float4*>(&Bs[kk * 64 + c4 * 4]) =
                *reinterpret_cast<const float4*>(&W[(size_t)(k0 + kk) * N + col0 + c4 * 4]);
        }
        __syncthreads();
#pragma unroll 8
        for (int kk = 0; kk < 32; kk++) {
            float4 a = *reinterpret_cast<const float4*>(&Ast[kk * 68 + ty * 4]);
            float4 bb = *reinterpret_cast<const float4*>(&Bs[kk * 64 + tx * 4]);
            acc[0][0] += a.x * bb.x; acc[0][1] += a.x * bb.y;
            acc[0][2] += a.x * bb.z; acc[0][3] += a.x * bb.w;
            acc[1][0] += a.y * bb.x; acc[1][1] += a.y * bb.y;
            acc[1][2] += a.y * bb.z; acc[1][3] += a.y * bb.w;
            acc[2][0] += a.z * bb.x; acc[2][1] += a.z * bb.y;
            acc[2][2] += a.z * bb.z; acc[2][3] += a.z * bb.w;
            acc[3][0] += a.w * bb.x; acc[3][1] += a.w * bb.y;
            acc[3][2] += a.w * bb.z; acc[3][3] += a.w * bb.w;
        }
        __syncthreads();
    }
#pragma unroll
    for (int i = 0; i < 4; i++) {
        int r = row0 + ty * 4 + i, c = col0 + tx * 4;
        float4 o;
        o.x = acc[i][0] + bias[c + 0];
        o.y = acc[i][1] + bias[c + 1];
        o.z = acc[i][2] + bias[c + 2];
        o.w = acc[i][3] + bias[c + 3];
        *reinterpret_cast<float4*>(&C[(size_t)r * N + c]) = o;
    }
}

// =====================================================================
// final: out[b][0..1] = leaky(bn2(Z2)) @ w3 + b3
// =====================================================================
__global__ void __launch_bounds__(256) final_kernel(
    const float* __restrict__ w3, const float* __restrict__ b3,
    float* __restrict__ out)
{
    int b = blockIdx.x, tid = threadIdx.x;
    int lane = tid & 31, w = tid >> 5;
    float v = g_Z2[b * 256 + tid] * g_sc2[tid] + g_sh2[tid];
    v = (v > 0.f) ? v : 0.1f * v;
    float a0 = v * w3[tid * 2 + 0];
    float a1 = v * w3[tid * 2 + 1];
#pragma unroll
    for (int o = 16; o > 0; o >>= 1) {
        a0 += __shfl_xor_sync(0xffffffffu, a0, o);
        a1 += __shfl_xor_sync(0xffffffffu, a1, o);
    }
    __shared__ float r0s[8], r1s[8];
    if (lane == 0) { r0s[w] = a0; r1s[w] = a1; }
    __syncthreads();
    if (tid == 0) {
        float s0 = 0.f, s1 = 0.f;
        for (int i = 0; i < 8; i++) { s0 += r0s[i]; s1 += r1s[i]; }
        out[b * 2 + 0] = s0 + b3[0];
        out[b * 2 + 1] = s1 + b3[1];
    }
}

// =====================================================================
extern "C" void kernel_launch(void* const* d_in, const int* in_sizes, int n_in,
                              void* d_out, int out_size)
{
    (void)in_sizes; (void)n_in; (void)out_size;
    const int*   uid   = (const int*)d_in[0];
    const int*   mid   = (const int*)d_in[1];
    const int*   cat   = (const int*)d_in[2];
    const int*   hmid  = (const int*)d_in[3];
    const int*   hcat  = (const int*)d_in[4];
    const int*   mask  = (const int*)d_in[5];
    const float* utab  = (const float*)d_in[6];
    const float* mtab  = (const float*)d_in[7];
    const float* ctab  = (const float*)d_in[8];
    const float* lw1   = (const float*)d_in[9];
    const float* lb1   = (const float*)d_in[10];
    const float* lw2   = (const float*)d_in[11];
    const float* lb2   = (const float*)d_in[12];
    const float* lw3   = (const float*)d_in[13];
    const float* lb3   = (const float*)d_in[14];
    const float* bn0g  = (const float*)d_in[15];
    const float* bn0b  = (const float*)d_in[16];
    const float* mw1   = (const float*)d_in[17];
    const float* mb1   = (const float*)d_in[18];
    const float* bn1g  = (const float*)d_in[19];
    const float* bn1b  = (const float*)d_in[20];
    const float* mw2   = (const float*)d_in[21];
    const float* mb2   = (const float*)d_in[22];
    const float* bn2g  = (const float*)d_in[23];
    const float* bn2b  = (const float*)d_in[24];
    const float* mw3   = (const float*)d_in[25];
    const float* mb3   = (const float*)d_in[26];
    float* out = (float*)d_out;

    static int attr_done = 0;
    if (!attr_done) {
        cudaFuncSetAttribute(k1_kernel, cudaFuncAttributeMaxDynamicSharedMemorySize,
                             (int)sizeof(SmemK1));
        cudaFuncSetAttribute(k2_kernel, cudaFuncAttributeMaxDynamicSharedMemorySize,
                             (int)sizeof(SmemK2));
        attr_done = 1;
    }

    float *sc0, *sh0, *sc1, *sh1, *sc2, *sh2, *X, *Z1, *Z2;
    cudaGetSymbolAddress((void**)&sc0, g_sc0);
    cudaGetSymbolAddress((void**)&sh0, g_sh0);
    cudaGetSymbolAddress((void**)&sc1, g_sc1);
    cudaGetSymbolAddress((void**)&sh1, g_sh1);
    cudaGetSymbolAddress((void**)&sc2, g_sc2);
    cudaGetSymbolAddress((void**)&sh2, g_sh2);
    cudaGetSymbolAddress((void**)&X,  g_X);
    cudaGetSymbolAddress((void**)&Z1, g_Z1);
    cudaGetSymbolAddress((void**)&Z2, g_Z2);

    prep_imgs<<<128, 256>>>(lw1, lw2);
    prep_w1ac<<<64, 256>>>(lw1);

    k1_kernel<<<BB, 256, sizeof(SmemK1)>>>(mid, cat, hmid, hcat, mtab, ctab, lb1);
    k2_kernel<<<BB, 256, sizeof(SmemK2)>>>(uid, mid, cat, hmid, hcat, mask,
                                           utab, mtab, ctab, lb2, lw3, lb3);

    stats_kernel<<<448 / 32, 256>>>(X, BB, 448, bn0g, bn0b, sc0, sh0);
    gemm_bn<<<dim3(512 / 64, BB / 64), 256>>>(X, mw1, mb1, sc0, sh0, 0, 448, 512, Z1);

    stats_kernel<<<512 / 32, 256>>>(Z1, BB, 512, bn1g, bn1b, sc1, sh1);
    gemm_bn<<<dim3(256 / 64, BB / 64), 256>>>(Z1, mw2, mb2, sc1, sh1, 1, 512, 256, Z2);

    stats_kernel<<<256 / 32, 256>>>(Z2, BB, 256, bn2g, bn2b, sc2, sh2);
    final_kernel<<<BB, 256>>>(mw3, mb3, out);
}

// round 12
// speedup vs baseline: 3.0001x; 1.3174x over previous
#include <cuda_runtime.h>
#include <cuda_fp16.h>
#include <math.h>
#include <stdint.h>

#define BB 1024
#define TT 200
#define EE 64

// ---------------- scratch (__device__ globals: allocation-free) ----------------
__device__ float g_X [BB * 448];
__device__ float g_Z1[BB * 512];
__device__ float g_Z2[BB * 256];
__device__ float g_sc0[448], g_sh0[448];
__device__ float g_sc1[512], g_sh1[512];
__device__ float g_sc2[256], g_sh2[256];
// fp16 operand images, plain [n][k] row-major packed as half2 along k
__device__ unsigned g_imgBbc[16384];   // (W1b - W1c)^T  [256][64 half2]
__device__ unsigned g_imgBd [16384];   // (W1d)^T        [256][64 half2]
__device__ unsigned g_imgW2T[16384];   // W2^T           [128][128 half2]
__device__ __half g_W1ach[128 * 256];  // W1a + W1c, [k][j] fp16

__device__ __forceinline__ float sigm(float x) { return 1.0f / (1.0f + __expf(-x)); }

__device__ __forceinline__ unsigned pack2(float a, float b) {
    __half2 h = __floats2half2_rn(a, b);
    return *reinterpret_cast<unsigned*>(&h);
}
__device__ __forceinline__ unsigned hfma2u(unsigned c2, unsigned d2, unsigned b2v) {
    __half2 r = __hfma2(*reinterpret_cast<__half2*>(&c2),
                        *reinterpret_cast<__half2*>(&d2),
                        *reinterpret_cast<__half2*>(&b2v));
    return *reinterpret_cast<unsigned*>(&r);
}

// warp-level HMMA: D(16x8,f32) += A(16x16,f16 row) * B(16x8,f16 col)
__device__ __forceinline__ void mma16816(float* d, const unsigned* a,
                                         unsigned b0, unsigned b1) {
    asm volatile(
        "mma.sync.aligned.m16n8k16.row.col.f32.f16.f16.f32 "
        "{%0,%1,%2,%3}, {%4,%5,%6,%7}, {%8,%9}, {%0,%1,%2,%3};"
        : "+f"(d[0]), "+f"(d[1]), "+f"(d[2]), "+f"(d[3])
        : "r"(a[0]), "r"(a[1]), "r"(a[2]), "r"(a[3]), "r"(b0), "r"(b1));
}

// =====================================================================
// prep kernels: b-invariant fp16 operand images
// =====================================================================
__global__ void __launch_bounds__(256) prep_imgs(const float* __restrict__ w1,
                                                 const float* __restrict__ w2)
{
    int gid = blockIdx.x * 256 + threadIdx.x;
    if (gid < 16384) {
        int j = gid >> 6, kk = gid & 63, k = kk * 2;
        float bc0 = w1[(128 + k) * 256 + j] - w1[(256 + k) * 256 + j];
        float bc1 = w1[(129 + k) * 256 + j] - w1[(257 + k) * 256 + j];
        g_imgBbc[gid] = pack2(bc0, bc1);
        g_imgBd [gid] = pack2(w1[(384 + k) * 256 + j], w1[(385 + k) * 256 + j]);
    } else {
        int t = gid - 16384;
        int j = t >> 7, kk = t & 127, k = kk * 2;
        g_imgW2T[t] = pack2(w2[k * 128 + j], w2[(k + 1) * 128 + j]);
    }
}

__global__ void __launch_bounds__(256) prep_w1ac(const float* __restrict__ w1)
{
    int gid = blockIdx.x * 256 + threadIdx.x;   // 16384 half2 elems
    int k = gid >> 7, j = (gid & 127) * 2;
    float a = w1[k * 256 + j]     + w1[(256 + k) * 256 + j];
    float b = w1[k * 256 + j + 1] + w1[(256 + k) * 256 + j + 1];
    reinterpret_cast<unsigned*>(g_W1ach)[gid] = pack2(a, b);
}

// =====================================================================
// FUSED per-b kernel:
//   phase A: build Weff (B region) + c1 + hist (A1), GEMM1 -> sigmoid -> A2 (smem)
//   phase B: load W2T into B region, GEMM2 + sigmoid + w3-dot -> aw
//   phase C: masked softmax, lau + masked-mean pooling, write X[b][448]
// smem layout (bytes):
//   [0,105600)        A2 : S1, half, 200 rows x LD2(264)
//   [105600,175232)   B  : Weff 256xLDB1(136) halves, then W2T 128xLD2(264)
//   [175232,229632)   A1 : hist, half, 200 rows x LDA1(136)
//                     (misc overlay at 175232 after GEMM1: aw/w3/b2/lau/hsum/red/scal)
//   [229632,230656)   c1s float[256]
//   [230656,230912)   curs2h unsigned[64]
//   pad to 231936 (GEMM pad rows 200-207 read garbage in-bounds; outputs guarded)
// =====================================================================
#define LDA1 136
#define LDB1 136
#define LD2  264
#define OFF_A2 0
#define OFF_B  105600
#define OFF_A1 175232
#define OFF_C1 229632
#define OFF_CH 230656
#define FUSED_SMEM 231936

__global__ void __launch_bounds__(256) fused_kernel(
    const int* __restrict__ uid, const int* __restrict__ mid,
    const int* __restrict__ catid,
    const int* __restrict__ hmid, const int* __restrict__ hcat,
    const int* __restrict__ mask,
    const float* __restrict__ user_table, const float* __restrict__ mat_table,
    const float* __restrict__ cat_table,
    const float* __restrict__ b1, const float* __restrict__ b2,
    const float* __restrict__ w3, const float* __restrict__ b3)
{
    extern __shared__ __align__(16) char sm[];
    __half* A2 = reinterpret_cast<__half*>(sm + OFF_A2);
    __half* Bw = reinterpret_cast<__half*>(sm + OFF_B);
    __half* A1 = reinterpret_cast<__half*>(sm + OFF_A1);
    float*  c1s = reinterpret_cast<float*>(sm + OFF_C1);
    unsigned* curs2h = reinterpret_cast<unsigned*>(sm + OFF_CH);
    // misc overlay (valid only after GEMM1 + sync)
    float* s_aw  = reinterpret_cast<float*>(sm + OFF_A1);
    float* s_w3  = reinterpret_cast<float*>(sm + OFF_A1 + 832);
    float* s_b2  = reinterpret_cast<float*>(sm + OFF_A1 + 1344);
    float* s_lau = reinterpret_cast<float*>(sm + OFF_A1 + 1856);
    float* s_hs  = reinterpret_cast<float*>(sm + OFF_A1 + 2368);
    float* s_red = reinterpret_cast<float*>(sm + OFF_A1 + 2880);
    float* s_scal= reinterpret_cast<float*>(sm + OFF_A1 + 3008); // max,sum,cnt

    const int b = blockIdx.x, tid = threadIdx.x;
    const int wid = tid >> 5, lane = tid & 31;
    const int g = lane >> 2, t4 = lane & 3;

    // ---- prologue: cur as half2 ----
    if (tid < 64) {
        int c0 = 2 * tid;
        float v0 = (c0 < 64) ? mat_table[(size_t)mid[b] * EE + c0]
                             : cat_table[(size_t)catid[b] * EE + c0 - 64];
        float v1 = (c0 + 1 < 64) ? mat_table[(size_t)mid[b] * EE + c0 + 1]
                                 : cat_table[(size_t)catid[b] * EE + c0 + 1 - 64];
        curs2h[tid] = pack2(v0, v1);
    }
    __syncthreads();

    // ---- c1[j] = b1[j] + sum_k cur[k] * W1ac[k][j] ----
    {
        const int j = tid;
        float acc = b1[j];
#pragma unroll 8
        for (int kk = 0; kk < 64; kk++) {
            unsigned cu = curs2h[kk];
            __half2 c2 = *reinterpret_cast<__half2*>(&cu);
            acc += __low2float(c2)  * __half2float(g_W1ach[(2 * kk) * 256 + j]);
            acc += __high2float(c2) * __half2float(g_W1ach[(2 * kk + 1) * 256 + j]);
        }
        c1s[j] = acc;
    }
    // ---- Weff^T [256][128] fp16 into B region ----
    {
        unsigned ch = curs2h[tid & 63];
        for (int t = tid; t < 16384; t += 256) {
            int j = t >> 6, kk = t & 63;
            *reinterpret_cast<unsigned*>(&Bw[j * LDB1 + kk * 2]) =
                hfma2u(ch, g_imgBd[t], g_imgBbc[t]);
        }
    }
    // ---- A1 = hist fp16, 200 rows ----
    for (int t = tid; t < 3200; t += 256) {
        int r = t >> 4, kg = t & 15;
        const float* src = (kg < 8)
            ? (mat_table + (size_t)hmid[b * TT + r] * EE + kg * 8)
            : (cat_table + (size_t)hcat[b * TT + r] * EE + (kg - 8) * 8);
        float4 f0 = *reinterpret_cast<const float4*>(src);
        float4 f1 = *reinterpret_cast<const float4*>(src + 4);
        uint4 o;
        o.x = pack2(f0.x, f0.y); o.y = pack2(f0.z, f0.w);
        o.z = pack2(f1.x, f1.y); o.w = pack2(f1.z, f1.w);
        *reinterpret_cast<uint4*>(&A1[r * LDA1 + kg * 8]) = o;
    }
    __syncthreads();

    // ---- GEMM1: 52 warp tiles m16 x n64, K=128 -> sigmoid -> A2 (smem) ----
    for (int tt = wid; tt < 52; tt += 8) {
        int m0 = (tt % 13) * 16, n0 = (tt / 13) * 64;
        float d[8][4];
#pragma unroll
        for (int i = 0; i < 8; i++) { d[i][0] = d[i][1] = d[i][2] = d[i][3] = 0.f; }
#pragma unroll 2
        for (int k0 = 0; k0 < 128; k0 += 16) {
            unsigned av[4];
            av[0] = *reinterpret_cast<const unsigned*>(&A1[(m0 + g)     * LDA1 + k0 + t4 * 2]);
            av[1] = *reinterpret_cast<const unsigned*>(&A1[(m0 + g + 8) * LDA1 + k0 + t4 * 2]);
            av[2] = *reinterpret_cast<const unsigned*>(&A1[(m0 + g)     * LDA1 + k0 + 8 + t4 * 2]);
            av[3] = *reinterpret_cast<const unsigned*>(&A1[(m0 + g + 8) * LDA1 + k0 + 8 + t4 * 2]);
#pragma unroll
            for (int n8 = 0; n8 < 8; n8++) {
                int nr = n0 + n8 * 8 + g;
                unsigned b0v = *reinterpret_cast<const unsigned*>(&Bw[nr * LDB1 + k0 + t4 * 2]);
                unsigned b1v = *reinterpret_cast<const unsigned*>(&Bw[nr * LDB1 + k0 + 8 + t4 * 2]);
                mma16816(d[n8], av, b0v, b1v);
            }
        }
        int r0 = m0 + g, r1 = m0 + g + 8;
#pragma unroll
        for (int n8 = 0; n8 < 8; n8++) {
            int col = n0 + n8 * 8 + t4 * 2;
            *reinterpret_cast<unsigned*>(&A2[r0 * LD2 + col]) =
                pack2(sigm(d[n8][0] + c1s[col]), sigm(d[n8][1] + c1s[col + 1]));
            if (r1 < TT)
                *reinterpret_cast<unsigned*>(&A2[r1 * LD2 + col]) =
                    pack2(sigm(d[n8][2] + c1s[col]), sigm(d[n8][3] + c1s[col + 1]));
        }
    }
    __syncthreads();

    // ---- phase B setup: W2T into B region (A1 region becomes misc) ----
    for (int t = tid; t < 16384; t += 256) {
        int j = t >> 7, kk = t & 127;
        *reinterpret_cast<unsigned*>(&Bw[j * LD2 + kk * 2]) = g_imgW2T[t];
    }
    float b3v = b3[0];
    if (tid < 128) {
        s_w3[tid] = w3[tid];
        s_b2[tid] = b2[tid];
        s_lau[tid] = 0.f;
        s_hs[tid] = 0.f;
    }
    if (tid < 208) s_aw[tid] = b3v;   // cover ALL 208 logit slots
    __syncthreads();

    // ---- GEMM2: 26 warp tiles m16 x n64, K=256 -> sigmoid + w3-dot -> aw ----
    for (int tt = wid; tt < 26; tt += 8) {
        int m0 = (tt % 13) * 16, n0 = (tt / 13) * 64;
        float d[8][4];
#pragma unroll
        for (int i = 0; i < 8; i++) { d[i][0] = d[i][1] = d[i][2] = d[i][3] = 0.f; }
#pragma unroll 2
        for (int k0 = 0; k0 < 256; k0 += 16) {
            unsigned av[4];
            av[0] = *reinterpret_cast<const unsigned*>(&A2[(m0 + g)     * LD2 + k0 + t4 * 2]);
            av[1] = *reinterpret_cast<const unsigned*>(&A2[(m0 + g + 8) * LD2 + k0 + t4 * 2]);
            av[2] = *reinterpret_cast<const unsigned*>(&A2[(m0 + g)     * LD2 + k0 + 8 + t4 * 2]);
            av[3] = *reinterpret_cast<const unsigned*>(&A2[(m0 + g + 8) * LD2 + k0 + 8 + t4 * 2]);
#pragma unroll
            for (int n8 = 0; n8 < 8; n8++) {
                int nr = n0 + n8 * 8 + g;
                unsigned b0v = *reinterpret_cast<const unsigned*>(&Bw[nr * LD2 + k0 + t4 * 2]);
                unsigned b1v = *reinterpret_cast<const unsigned*>(&Bw[nr * LD2 + k0 + 8 + t4 * 2]);
                mma16816(d[n8], av, b0v, b1v);
            }
        }
        float p0 = 0.f, p1 = 0.f;
#pragma unroll
        for (int n8 = 0; n8 < 8; n8++) {
            int c = n0 + n8 * 8 + t4 * 2;
            p0 += sigm(d[n8][0] + s_b2[c]) * s_w3[c]
                + sigm(d[n8][1] + s_b2[c + 1]) * s_w3[c + 1];
            p1 += sigm(d[n8][2] + s_b2[c]) * s_w3[c]
                + sigm(d[n8][3] + s_b2[c + 1]) * s_w3[c + 1];
        }
        p0 += __shfl_xor_sync(0xffffffffu, p0, 1);
        p0 += __shfl_xor_sync(0xffffffffu, p0, 2);
        p1 += __shfl_xor_sync(0xffffffffu, p1, 1);
        p1 += __shfl_xor_sync(0xffffffffu, p1, 2);
        if (t4 == 0) {
            atomicAdd(&s_aw[m0 + g], p0);
            if (m0 + g + 8 < TT) atomicAdd(&s_aw[m0 + g + 8], p1);
        }
    }
    __syncthreads();

    // ---- masked softmax over t ----
    int mk = (tid < TT) ? mask[b * TT + tid] : 0;
    {
        float v = -3.0e38f;
        if (tid < TT && mk) v = s_aw[tid];
#pragma unroll
        for (int o = 16; o > 0; o >>= 1)
            v = fmaxf(v, __shfl_xor_sync(0xffffffffu, v, o));
        if (lane == 0) s_red[wid] = v;
        __syncthreads();
        if (tid == 0) {
            float m = s_red[0];
            for (int i = 1; i < 8; i++) m = fmaxf(m, s_red[i]);
            s_scal[0] = m;
        }
        __syncthreads();

        float e = 0.f, cf = 0.f;
        if (tid < TT && mk) { e = __expf(s_aw[tid] - s_scal[0]); cf = 1.f; }
        float se = e, scf = cf;
#pragma unroll
        for (int o = 16; o > 0; o >>= 1) {
            se  += __shfl_xor_sync(0xffffffffu, se, o);
            scf += __shfl_xor_sync(0xffffffffu, scf, o);
        }
        if (lane == 0) { s_red[wid] = se; s_red[16 + wid] = scf; }
        __syncthreads();
        if (tid == 0) {
            float ss = 0.f, cc = 0.f;
            for (int i = 0; i < 8; i++) { ss += s_red[i]; cc += s_red[16 + i]; }
            s_scal[1] = ss; s_scal[2] = cc;
        }
        __syncthreads();
        if (tid < TT) s_aw[tid] = e / s_scal[1];
        __syncthreads();
    }

    // ---- lau + masked sum over history ----
    {
        int col = tid & 127, half = tid >> 7;
        const float* tab = (col < 64) ? mat_table : cat_table;
        const int* hidx = (col < 64) ? hmid : hcat;
        int coff = (col < 64) ? col : (col - 64);
        float al = 0.f, ah = 0.f;
        for (int t2 = half; t2 < TT; t2 += 2) {
            int row = hidx[b * TT + t2];
            float h = tab[(size_t)row * EE + coff];
            al += s_aw[t2] * h;
            ah += (float)mask[b * TT + t2] * h;
        }
        atomicAdd(&s_lau[col], al);
        atomicAdd(&s_hs[col], ah);
    }
    __syncthreads();

    // ---- write X row: [u(64), cur(128), lau(128), hmean(128)] ----
    {
        float inv = 1.0f / s_scal[2];
        int ub = uid[b];
        for (int i = tid; i < 448; i += 256) {
            float v;
            if (i < 64)       v = user_table[(size_t)ub * EE + i];
            else if (i < 192) {
                int c = i - 64;
                v = (c < 64) ? mat_table[(size_t)mid[b] * EE + c]
                             : cat_table[(size_t)catid[b] * EE + c - 64];
            }
            else if (i < 320) v = s_lau[i - 192];
            else              v = s_hs[i - 320] * inv;
            g_X[b * 448 + i] = v;
        }
    }
}

// =====================================================================
// stats: per-column mean/var over 1024 rows -> sc/sh affine
// =====================================================================
__global__ void __launch_bounds__(256) stats_kernel(
    const float* __restrict__ Z, int rows, int cols,
    const float* __restrict__ g, const float* __restrict__ bta,
    float* __restrict__ sc, float* __restrict__ sh)
{
    int tx = threadIdx.x & 31, ty = threadIdx.x >> 5;
    int col = blockIdx.x * 32 + tx;
    float su = 0.f, sq = 0.f;
    for (int r = ty; r < rows; r += 8) {
        float v = Z[(size_t)r * cols + col];
        su += v; sq += v * v;
    }
    __shared__ float ss[8][32], sqq[8][32];
    ss[ty][tx] = su; sqq[ty][tx] = sq;
    __syncthreads();
    if (ty == 0) {
        for (int i = 1; i < 8; i++) { su += ss[i][tx]; sq += sqq[i][tx]; }
        float inv = 1.0f / (float)rows;
        float mu = su * inv;
        float var = sq * inv - mu * mu;
        float scv = g[col] * rsqrtf(var + 1e-5f);
        sc[col] = scv;
        sh[col] = bta[col] - mu * scv;
    }
}

// =====================================================================
// gemm_bn32: C[1024xN] = f(A) @ W + bias; 32x64 tile, double-buffered
// =====================================================================
__global__ void __launch_bounds__(256) gemm_bn32(
    const float* __restrict__ A, const float* __restrict__ W,
    const float* __restrict__ bias, const float* __restrict__ sc,
    const float* __restrict__ sh, int leaky, int K, int N,
    float* __restrict__ C)
{
    __shared__ __align__(16) float Ast[2][32 * 33];
    __shared__ __align__(16) float Bs[2][32 * 64];
    int tid = threadIdx.x;
    int row0 = blockIdx.y * 32, col0 = blockIdx.x * 64;
    int ty = tid >> 4, tx = tid & 15;
    float acc[2][4];
#pragma unroll
    for (int i = 0; i < 2; i++)
        for (int j = 0; j < 4; j++) acc[i][j] = 0.f;

    // prologue load into buffer 0
    {
#pragma unroll
        for (int l = 0; l < 4; l++) {
            int i = tid + l * 256;
            int kk = i & 31, r = i >> 5;
            float v = A[(size_t)(row0 + r) * K + kk];
            v = v * sc[kk] + sh[kk];
            if (leaky) v = (v > 0.f) ? v : 0.1f * v;
            Ast[0][kk * 33 + r] = v;
        }
#pragma unroll
        for (int l = 0; l < 2; l++) {
            int i = tid + l * 256;
            int kk = i >> 4, c4 = i & 15;
            *reinterpret_cast<float4*>(&Bs[0][kk * 64 + c4 * 4]) =
                *reinterpret_cast<const float4*>(&W[(size_t)kk * N + col0 + c4 * 4]);
        }
    }
    __syncthreads();

    int cur = 0;
    for (int k0 = 0; k0 < K; k0 += 32) {
        int nxt = cur ^ 1;
        if (k0 + 32 < K) {
#pragma unroll
            for (int l = 0; l < 4; l++) {
                int i = tid + l * 256;
                int kk = i & 31, r = i >> 5;
                int k = k0 + 32 + kk;
                float v = A[(size_t)(row0 + r) * K + k];
                v = v * sc[k] + sh[k];
                if (leaky) v = (v > 0.f) ? v : 0.1f * v;
                Ast[nxt][kk * 33 + r] = v;
            }
#pragma unroll
            for (int l = 0; l < 2; l++) {
                int i = tid + l * 256;
                int kk = i >> 4, c4 = i & 15;
                *reinterpret_cast<float4*>(&Bs[nxt][kk * 64 + c4 * 4]) =
                    *reinterpret_cast<const float4*>(&W[(size_t)(k0 + 32 + kk) * N + col0 + c4 * 4]);
            }
        }
#pragma unroll 8
        for (int kk = 0; kk < 32; kk++) {
            float a0 = Ast[cur][kk * 33 + ty * 2];
            float a1 = Ast[cur][kk * 33 + ty * 2 + 1];
            float4 bb = *reinterpret_cast<const float4*>(&Bs[cur][kk * 64 + tx * 4]);
            acc[0][0] += a0 * bb.x; acc[0][1] += a0 * bb.y;
            acc[0][2] += a0 * bb.z; acc[0][3] += a0 * bb.w;
            acc[1][0] += a1 * bb.x; acc[1][1] += a1 * bb.y;
            acc[1][2] += a1 * bb.z; acc[1][3] += a1 * bb.w;
        }
        __syncthreads();
        cur = nxt;
    }
#pragma unroll
    for (int i = 0; i < 2; i++) {
        int r = row0 + ty * 2 + i, c = col0 + tx * 4;
        float4 o;
        o.x = acc[i][0] + bias[c + 0];
        o.y = acc[i][1] + bias[c + 1];
        o.z = acc[i][2] + bias[c + 2];
        o.w = acc[i][3] + bias[c + 3];
        *reinterpret_cast<float4*>(&C[(size_t)r * N + c]) = o;
    }
}

// =====================================================================
// final: out[b][0..1] = leaky(bn2(Z2)) @ w3 + b3
// =====================================================================
__global__ void __launch_bounds__(256) final_kernel(
    const float* __restrict__ w3, const float* __restrict__ b3,
    float* __restrict__ out)
{
    int b = blockIdx.x, tid = threadIdx.x;
    int lane = tid & 31, w = tid >> 5;
    float v = g_Z2[b * 256 + tid] * g_sc2[tid] + g_sh2[tid];
    v = (v > 0.f) ? v : 0.1f * v;
    float a0 = v * w3[tid * 2 + 0];
    float a1 = v * w3[tid * 2 + 1];
#pragma unroll
    for (int o = 16; o > 0; o >>= 1) {
        a0 += __shfl_xor_sync(0xffffffffu, a0, o);
        a1 += __shfl_xor_sync(0xffffffffu, a1, o);
    }
    __shared__ float r0s[8], r1s[8];
    if (lane == 0) { r0s[w] = a0; r1s[w] = a1; }
    __syncthreads();
    if (tid == 0) {
        float s0 = 0.f, s1 = 0.f;
        for (int i = 0; i < 8; i++) { s0 += r0s[i]; s1 += r1s[i]; }
        out[b * 2 + 0] = s0 + b3[0];
        out[b * 2 + 1] = s1 + b3[1];
    }
}

// =====================================================================
extern "C" void kernel_launch(void* const* d_in, const int* in_sizes, int n_in,
                              void* d_out, int out_size)
{
    (void)in_sizes; (void)n_in; (void)out_size;
    const int*   uid   = (const int*)d_in[0];
    const int*   mid   = (const int*)d_in[1];
    const int*   cat   = (const int*)d_in[2];
    const int*   hmid  = (const int*)d_in[3];
    const int*   hcat  = (const int*)d_in[4];
    const int*   mask  = (const int*)d_in[5];
    const float* utab  = (const float*)d_in[6];
    const float* mtab  = (const float*)d_in[7];
    const float* ctab  = (const float*)d_in[8];
    const float* lw1   = (const float*)d_in[9];
    const float* lb1   = (const float*)d_in[10];
    const float* lw2   = (const float*)d_in[11];
    const float* lb2   = (const float*)d_in[12];
    const float* lw3   = (const float*)d_in[13];
    const float* lb3   = (const float*)d_in[14];
    const float* bn0g  = (const float*)d_in[15];
    const float* bn0b  = (const float*)d_in[16];
    const float* mw1   = (const float*)d_in[17];
    const float* mb1   = (const float*)d_in[18];
    const float* bn1g  = (const float*)d_in[19];
    const float* bn1b  = (const float*)d_in[20];
    const float* mw2   = (const float*)d_in[21];
    const float* mb2   = (const float*)d_in[22];
    const float* bn2g  = (const float*)d_in[23];
    const float* bn2b  = (const float*)d_in[24];
    const float* mw3   = (const float*)d_in[25];
    const float* mb3   = (const float*)d_in[26];
    float* out = (float*)d_out;

    static int attr_done = 0;
    if (!attr_done) {
        cudaFuncSetAttribute(fused_kernel, cudaFuncAttributeMaxDynamicSharedMemorySize,
                             FUSED_SMEM);
        attr_done = 1;
    }

    float *sc0, *sh0, *sc1, *sh1, *sc2, *sh2, *X, *Z1, *Z2;
    cudaGetSymbolAddress((void**)&sc0, g_sc0);
    cudaGetSymbolAddress((void**)&sh0, g_sh0);
    cudaGetSymbolAddress((void**)&sc1, g_sc1);
    cudaGetSymbolAddress((void**)&sh1, g_sh1);
    cudaGetSymbolAddress((void**)&sc2, g_sc2);
    cudaGetSymbolAddress((void**)&sh2, g_sh2);
    cudaGetSymbolAddress((void**)&X,  g_X);
    cudaGetSymbolAddress((void**)&Z1, g_Z1);
    cudaGetSymbolAddress((void**)&Z2, g_Z2);

    prep_imgs<<<128, 256>>>(lw1, lw2);
    prep_w1ac<<<64, 256>>>(lw1);

    fused_kernel<<<BB, 256, FUSED_SMEM>>>(uid, mid, cat, hmid, hcat, mask,
                                          utab, mtab, ctab, lb1, lb2, lw3, lb3);

    stats_kernel<<<448 / 32, 256>>>(X, BB, 448, bn0g, bn0b, sc0, sh0);
    gemm_bn32<<<dim3(512 / 64, BB / 32), 256>>>(X, mw1, mb1, sc0, sh0, 0, 448, 512, Z1);

    stats_kernel<<<512 / 32, 256>>>(Z1, BB, 512, bn1g, bn1b, sc1, sh1);
    gemm_bn32<<<dim3(256 / 64, BB / 32), 256>>>(Z1, mw2, mb2, sc1, sh1, 1, 512, 256, Z2);

    stats_kernel<<<256 / 32, 256>>>(Z2, BB, 256, bn2g, bn2b, sc2, sh2);
    final_kernel<<<BB, 256>>>(mw3, mb3, out);
}

// round 13
// speedup vs baseline: 4.0658x; 1.3552x over previous
#include <cuda_runtime.h>
#include <cuda_fp16.h>
#include <math.h>
#include <stdint.h>

#define BB 1024
#define TT 200
#define EE 64

// ---------------- scratch (__device__ globals: allocation-free) ----------------
__device__ float g_X [BB * 448];
__device__ float g_Z1[BB * 512];
__device__ float g_Z2[BB * 256];
__device__ float g_sc0[448], g_sh0[448];
__device__ float g_sc1[512], g_sh1[512];
__device__ float g_sc2[256], g_sh2[256];
// fp16 operand images, plain [n][k] row-major packed as half2 along k
__device__ unsigned g_imgBbc[16384];   // (W1b - W1c)^T  [256][64 half2]
__device__ unsigned g_imgBd [16384];   // (W1d)^T        [256][64 half2]
__device__ unsigned g_imgW2T[16384];   // W2^T           [128][128 half2]
__device__ unsigned g_W1ach[128 * 128]; // W1a + W1c, [k][j] as half2 pairs along j

__device__ __forceinline__ float sigm(float x) { return 1.0f / (1.0f + __expf(-x)); }

__device__ __forceinline__ unsigned pack2(float a, float b) {
    __half2 h = __floats2half2_rn(a, b);
    return *reinterpret_cast<unsigned*>(&h);
}
__device__ __forceinline__ unsigned hfma2u(unsigned c2, unsigned d2, unsigned b2v) {
    __half2 r = __hfma2(*reinterpret_cast<__half2*>(&c2),
                        *reinterpret_cast<__half2*>(&d2),
                        *reinterpret_cast<__half2*>(&b2v));
    return *reinterpret_cast<unsigned*>(&r);
}

// warp-level HMMA: D(16x8,f32) += A(16x16,f16 row) * B(16x8,f16 col)
__device__ __forceinline__ void mma16816(float* d, const unsigned* a,
                                         unsigned b0, unsigned b1) {
    asm volatile(
        "mma.sync.aligned.m16n8k16.row.col.f32.f16.f16.f32 "
        "{%0,%1,%2,%3}, {%4,%5,%6,%7}, {%8,%9}, {%0,%1,%2,%3};"
        : "+f"(d[0]), "+f"(d[1]), "+f"(d[2]), "+f"(d[3])
        : "r"(a[0]), "r"(a[1]), "r"(a[2]), "r"(a[3]), "r"(b0), "r"(b1));
}

// =====================================================================
// prep kernels: b-invariant fp16 operand images
// =====================================================================
__global__ void __launch_bounds__(256) prep_imgs(const float* __restrict__ w1,
                                                 const float* __restrict__ w2)
{
    int gid = blockIdx.x * 256 + threadIdx.x;
    if (gid < 16384) {
        int j = gid >> 6, kk = gid & 63, k = kk * 2;
        float bc0 = w1[(128 + k) * 256 + j] - w1[(256 + k) * 256 + j];
        float bc1 = w1[(129 + k) * 256 + j] - w1[(257 + k) * 256 + j];
        g_imgBbc[gid] = pack2(bc0, bc1);
        g_imgBd [gid] = pack2(w1[(384 + k) * 256 + j], w1[(385 + k) * 256 + j]);
    } else {
        int t = gid - 16384;
        int j = t >> 7, kk = t & 127, k = kk * 2;
        g_imgW2T[t] = pack2(w2[k * 128 + j], w2[(k + 1) * 128 + j]);
    }
}

__global__ void __launch_bounds__(256) prep_w1ac(const float* __restrict__ w1)
{
    int gid = blockIdx.x * 256 + threadIdx.x;   // 16384 half2 elems, [k][j2]
    int k = gid >> 7, j = (gid & 127) * 2;
    float a = w1[k * 256 + j]     + w1[(256 + k) * 256 + j];
    float b = w1[k * 256 + j + 1] + w1[(256 + k) * 256 + j + 1];
    g_W1ach[gid] = pack2(a, b);
}

// =====================================================================
// FUSED per-b kernel (512 threads, 16 warps):
//   phase A: build Weff (B region) + c1 + hist (A1), GEMM1 -> sigmoid -> A2 (smem)
//   phase B: load W2T into B region, GEMM2 + sigmoid + w3-dot -> aw
//   phase C: masked softmax, lau + masked-mean pooling, write X[b][448]
// smem layout (bytes):
//   [0,105600)        A2 : S1, half, 200 rows x LD2(264)
//   [105600,175232)   B  : Weff 256xLDB1(136) halves, then W2T 128xLD2(264)
//   [175232,229632)   A1 : hist, half, 200 rows x LDA1(136)
//                     (misc overlay at 175232 after GEMM1)
//   [229632,230656)   c1s float[256]
//   [230656,230912)   curs2h unsigned[64]
//   pad to 231936 (GEMM pad rows 200-207 read garbage in-bounds; outputs guarded)
// =====================================================================
#define LDA1 136
#define LDB1 136
#define LD2  264
#define OFF_A2 0
#define OFF_B  105600
#define OFF_A1 175232
#define OFF_C1 229632
#define OFF_CH 230656
#define FUSED_SMEM 231936
#define FTH 512

__global__ void __launch_bounds__(FTH) fused_kernel(
    const int* __restrict__ uid, const int* __restrict__ mid,
    const int* __restrict__ catid,
    const int* __restrict__ hmid, const int* __restrict__ hcat,
    const int* __restrict__ mask,
    const float* __restrict__ user_table, const float* __restrict__ mat_table,
    const float* __restrict__ cat_table,
    const float* __restrict__ b1, const float* __restrict__ b2,
    const float* __restrict__ w3, const float* __restrict__ b3)
{
    extern __shared__ __align__(16) char sm[];
    __half* A2 = reinterpret_cast<__half*>(sm + OFF_A2);
    __half* Bw = reinterpret_cast<__half*>(sm + OFF_B);
    __half* A1 = reinterpret_cast<__half*>(sm + OFF_A1);
    float*  c1s = reinterpret_cast<float*>(sm + OFF_C1);
    unsigned* curs2h = reinterpret_cast<unsigned*>(sm + OFF_CH);
    // misc overlay (valid only after GEMM1 + sync)
    float* s_aw  = reinterpret_cast<float*>(sm + OFF_A1);
    float* s_w3  = reinterpret_cast<float*>(sm + OFF_A1 + 832);
    float* s_b2  = reinterpret_cast<float*>(sm + OFF_A1 + 1344);
    float* s_lau = reinterpret_cast<float*>(sm + OFF_A1 + 1856);
    float* s_hs  = reinterpret_cast<float*>(sm + OFF_A1 + 2368);
    float* s_red = reinterpret_cast<float*>(sm + OFF_A1 + 2880);
    float* s_scal= reinterpret_cast<float*>(sm + OFF_A1 + 3008); // max,sum,cnt

    const int b = blockIdx.x, tid = threadIdx.x;
    const int wid = tid >> 5, lane = tid & 31;
    const int g = lane >> 2, t4 = lane & 3;

    // ---- prologue: cur as half2 ----
    if (tid < 64) {
        int c0 = 2 * tid;
        float v0 = (c0 < 64) ? mat_table[(size_t)mid[b] * EE + c0]
                             : cat_table[(size_t)catid[b] * EE + c0 - 64];
        float v1 = (c0 + 1 < 64) ? mat_table[(size_t)mid[b] * EE + c0 + 1]
                                 : cat_table[(size_t)catid[b] * EE + c0 + 1 - 64];
        curs2h[tid] = pack2(v0, v1);
    }
    __syncthreads();

    // ---- c1 (warps 0-3): c1[j] = b1[j] + sum_k cur[k] * W1ac[k][j], half2 over j ----
    if (tid < 128) {
        const int j2 = tid;
        float acc0 = b1[2 * j2], acc1 = b1[2 * j2 + 1];
#pragma unroll 8
        for (int kk = 0; kk < 64; kk++) {
            unsigned cu = curs2h[kk];
            __half2 c2 = *reinterpret_cast<__half2*>(&cu);
            float clo = __low2float(c2), chi = __high2float(c2);
            unsigned w0 = g_W1ach[(2 * kk) * 128 + j2];
            unsigned w1v = g_W1ach[(2 * kk + 1) * 128 + j2];
            __half2 h0 = *reinterpret_cast<__half2*>(&w0);
            __half2 h1 = *reinterpret_cast<__half2*>(&w1v);
            acc0 += clo * __low2float(h0)  + chi * __low2float(h1);
            acc1 += clo * __high2float(h0) + chi * __high2float(h1);
        }
        c1s[2 * j2] = acc0;
        c1s[2 * j2 + 1] = acc1;
    }
    // ---- Weff^T [256][128] fp16 into B region ----
    {
        unsigned ch = curs2h[tid & 63];
        for (int t = tid; t < 16384; t += FTH) {
            int j = t >> 6, kk = t & 63;
            *reinterpret_cast<unsigned*>(&Bw[j * LDB1 + kk * 2]) =
                hfma2u(ch, g_imgBd[t], g_imgBbc[t]);
        }
    }
    // ---- A1 = hist fp16, 200 rows ----
    for (int t = tid; t < 3200; t += FTH) {
        int r = t >> 4, kg = t & 15;
        const float* src = (kg < 8)
            ? (mat_table + (size_t)hmid[b * TT + r] * EE + kg * 8)
            : (cat_table + (size_t)hcat[b * TT + r] * EE + (kg - 8) * 8);
        float4 f0 = *reinterpret_cast<const float4*>(src);
        float4 f1 = *reinterpret_cast<const float4*>(src + 4);
        uint4 o;
        o.x = pack2(f0.x, f0.y); o.y = pack2(f0.z, f0.w);
        o.z = pack2(f1.x, f1.y); o.w = pack2(f1.z, f1.w);
        *reinterpret_cast<uint4*>(&A1[r * LDA1 + kg * 8]) = o;
    }
    __syncthreads();

    // ---- GEMM1: 104 warp tiles m16 x n32, K=128 -> sigmoid -> A2 (smem) ----
    for (int tt = wid; tt < 104; tt += 16) {
        int m0 = (tt % 13) * 16, n0 = (tt / 13) * 32;
        float d[4][4];
#pragma unroll
        for (int i = 0; i < 4; i++) { d[i][0] = d[i][1] = d[i][2] = d[i][3] = 0.f; }
#pragma unroll 2
        for (int k0 = 0; k0 < 128; k0 += 16) {
            unsigned av[4];
            av[0] = *reinterpret_cast<const unsigned*>(&A1[(m0 + g)     * LDA1 + k0 + t4 * 2]);
            av[1] = *reinterpret_cast<const unsigned*>(&A1[(m0 + g + 8) * LDA1 + k0 + t4 * 2]);
            av[2] = *reinterpret_cast<const unsigned*>(&A1[(m0 + g)     * LDA1 + k0 + 8 + t4 * 2]);
            av[3] = *reinterpret_cast<const unsigned*>(&A1[(m0 + g + 8) * LDA1 + k0 + 8 + t4 * 2]);
#pragma unroll
            for (int n8 = 0; n8 < 4; n8++) {
                int nr = n0 + n8 * 8 + g;
                unsigned b0v = *reinterpret_cast<const unsigned*>(&Bw[nr * LDB1 + k0 + t4 * 2]);
                unsigned b1v = *reinterpret_cast<const unsigned*>(&Bw[nr * LDB1 + k0 + 8 + t4 * 2]);
                mma16816(d[n8], av, b0v, b1v);
            }
        }
        int r0 = m0 + g, r1 = m0 + g + 8;
#pragma unroll
        for (int n8 = 0; n8 < 4; n8++) {
            int col = n0 + n8 * 8 + t4 * 2;
            *reinterpret_cast<unsigned*>(&A2[r0 * LD2 + col]) =
                pack2(sigm(d[n8][0] + c1s[col]), sigm(d[n8][1] + c1s[col + 1]));
            if (r1 < TT)
                *reinterpret_cast<unsigned*>(&A2[r1 * LD2 + col]) =
                    pack2(sigm(d[n8][2] + c1s[col]), sigm(d[n8][3] + c1s[col + 1]));
        }
    }
    __syncthreads();

    // ---- phase B setup: W2T into B region (A1 region becomes misc) ----
    for (int t = tid; t < 16384; t += FTH) {
        int j = t >> 7, kk = t & 127;
        *reinterpret_cast<unsigned*>(&Bw[j * LD2 + kk * 2]) = g_imgW2T[t];
    }
    float b3v = b3[0];
    if (tid < 128) {
        s_w3[tid] = w3[tid];
        s_b2[tid] = b2[tid];
        s_lau[tid] = 0.f;
        s_hs[tid] = 0.f;
    }
    if (tid < 208) s_aw[tid] = b3v;
    __syncthreads();

    // ---- GEMM2: 52 warp tiles m16 x n32, K=256 -> sigmoid + w3-dot -> aw ----
    for (int tt = wid; tt < 52; tt += 16) {
        int m0 = (tt % 13) * 16, n0 = (tt / 13) * 32;
        float d[4][4];
#pragma unroll
        for (int i = 0; i < 4; i++) { d[i][0] = d[i][1] = d[i][2] = d[i][3] = 0.f; }
#pragma unroll 2
        for (int k0 = 0; k0 < 256; k0 += 16) {
            unsigned av[4];
            av[0] = *reinterpret_cast<const unsigned*>(&A2[(m0 + g)     * LD2 + k0 + t4 * 2]);
            av[1] = *reinterpret_cast<const unsigned*>(&A2[(m0 + g + 8) * LD2 + k0 + t4 * 2]);
            av[2] = *reinterpret_cast<const unsigned*>(&A2[(m0 + g)     * LD2 + k0 + 8 + t4 * 2]);
            av[3] = *reinterpret_cast<const unsigned*>(&A2[(m0 + g + 8) * LD2 + k0 + 8 + t4 * 2]);
#pragma unroll
            for (int n8 = 0; n8 < 4; n8++) {
                int nr = n0 + n8 * 8 + g;
                unsigned b0v = *reinterpret_cast<const unsigned*>(&Bw[nr * LD2 + k0 + t4 * 2]);
                unsigned b1v = *reinterpret_cast<const unsigned*>(&Bw[nr * LD2 + k0 + 8 + t4 * 2]);
                mma16816(d[n8], av, b0v, b1v);
            }
        }
        float p0 = 0.f, p1 = 0.f;
#pragma unroll
        for (int n8 = 0; n8 < 4; n8++) {
            int c = n0 + n8 * 8 + t4 * 2;
            p0 += sigm(d[n8][0] + s_b2[c]) * s_w3[c]
                + sigm(d[n8][1] + s_b2[c + 1]) * s_w3[c + 1];
            p1 += sigm(d[n8][2] + s_b2[c]) * s_w3[c]
                + sigm(d[n8][3] + s_b2[c + 1]) * s_w3[c + 1];
        }
        p0 += __shfl_xor_sync(0xffffffffu, p0, 1);
        p0 += __shfl_xor_sync(0xffffffffu, p0, 2);
        p1 += __shfl_xor_sync(0xffffffffu, p1, 1);
        p1 += __shfl_xor_sync(0xffffffffu, p1, 2);
        if (t4 == 0) {
            atomicAdd(&s_aw[m0 + g], p0);
            if (m0 + g + 8 < TT) atomicAdd(&s_aw[m0 + g + 8], p1);
        }
    }
    __syncthreads();

    // ---- masked softmax over t ----
    int mk = (tid < TT) ? mask[b * TT + tid] : 0;
    {
        float v = -3.0e38f;
        if (tid < TT && mk) v = s_aw[tid];
#pragma unroll
        for (int o = 16; o > 0; o >>= 1)
            v = fmaxf(v, __shfl_xor_sync(0xffffffffu, v, o));
        if (lane == 0) s_red[wid] = v;
        __syncthreads();
        if (tid == 0) {
            float m = s_red[0];
            for (int i = 1; i < 16; i++) m = fmaxf(m, s_red[i]);
            s_scal[0] = m;
        }
        __syncthreads();

        float e = 0.f, cf = 0.f;
        if (tid < TT && mk) { e = __expf(s_aw[tid] - s_scal[0]); cf = 1.f; }
        float se = e, scf = cf;
#pragma unroll
        for (int o = 16; o > 0; o >>= 1) {
            se  += __shfl_xor_sync(0xffffffffu, se, o);
            scf += __shfl_xor_sync(0xffffffffu, scf, o);
        }
        if (lane == 0) { s_red[wid] = se; s_red[16 + wid] = scf; }
        __syncthreads();
        if (tid == 0) {
            float ss = 0.f, cc = 0.f;
            for (int i = 0; i < 16; i++) { ss += s_red[i]; cc += s_red[16 + i]; }
            s_scal[1] = ss; s_scal[2] = cc;
        }
        __syncthreads();
        if (tid < TT) s_aw[tid] = e / s_scal[1];
        __syncthreads();
    }

    // ---- lau + masked sum over history (4 t-slices per column) ----
    {
        int col = tid & 127, quarter = tid >> 7;
        const float* tab = (col < 64) ? mat_table : cat_table;
        const int* hidx = (col < 64) ? hmid : hcat;
        int coff = (col < 64) ? col : (col - 64);
        float al = 0.f, ah = 0.f;
        for (int t2 = quarter; t2 < TT; t2 += 4) {
            int row = hidx[b * TT + t2];
            float h = tab[(size_t)row * EE + coff];
            al += s_aw[t2] * h;
            ah += (float)mask[b * TT + t2] * h;
        }
        atomicAdd(&s_lau[col], al);
        atomicAdd(&s_hs[col], ah);
    }
    __syncthreads();

    // ---- write X row: [u(64), cur(128), lau(128), hmean(128)] ----
    if (tid < 448) {
        float inv = 1.0f / s_scal[2];
        int i = tid;
        float v;
        if (i < 64)       v = user_table[(size_t)uid[b] * EE + i];
        else if (i < 192) {
            int c = i - 64;
            v = (c < 64) ? mat_table[(size_t)mid[b] * EE + c]
                         : cat_table[(size_t)catid[b] * EE + c - 64];
        }
        else if (i < 320) v = s_lau[i - 192];
        else              v = s_hs[i - 320] * inv;
        g_X[b * 448 + i] = v;
    }
}

// =====================================================================
// stats: per-column mean/var over 1024 rows -> sc/sh affine (1024 thr)
// =====================================================================
__global__ void __launch_bounds__(1024) stats_kernel(
    const float* __restrict__ Z, int rows, int cols,
    const float* __restrict__ g, const float* __restrict__ bta,
    float* __restrict__ sc, float* __restrict__ sh)
{
    int tx = threadIdx.x & 31, ty = threadIdx.x >> 5;   // 32 row-groups x 32 cols
    int col = blockIdx.x * 32 + tx;
    float su = 0.f, sq = 0.f;
    for (int r = ty; r < rows; r += 32) {
        float v = Z[(size_t)r * cols + col];
        su += v; sq += v * v;
    }
    __shared__ float ss[32][32], sqq[32][32];
    ss[ty][tx] = su; sqq[ty][tx] = sq;
    __syncthreads();
    if (ty == 0) {
        for (int i = 1; i < 32; i++) { su += ss[i][tx]; sq += sqq[i][tx]; }
        float inv = 1.0f / (float)rows;
        float mu = su * inv;
        float var = sq * inv - mu * mu;
        float scv = g[col] * rsqrtf(var + 1e-5f);
        sc[col] = scv;
        sh[col] = bta[col] - mu * scv;
    }
}

// =====================================================================
// gemm_bn32: C[1024xN] = f(A) @ W + bias; 32x64 tile, double-buffered
// =====================================================================
__global__ void __launch_bounds__(256) gemm_bn32(
    const float* __restrict__ A, const float* __restrict__ W,
    const float* __restrict__ bias, const float* __restrict__ sc,
    const float* __restrict__ sh, int leaky, int K, int N,
    float* __restrict__ C)
{
    __shared__ __align__(16) float Ast[2][32 * 33];
    __shared__ __align__(16) float Bs[2][32 * 64];
    int tid = threadIdx.x;
    int row0 = blockIdx.y * 32, col0 = blockIdx.x * 64;
    int ty = tid >> 4, tx = tid & 15;
    float acc[2][4];
#pragma unroll
    for (int i = 0; i < 2; i++)
        for (int j = 0; j < 4; j++) acc[i][j] = 0.f;

    {
#pragma unroll
        for (int l = 0; l < 4; l++) {
            int i = tid + l * 256;
            int kk = i & 31, r = i >> 5;
            float v = A[(size_t)(row0 + r) * K + kk];
            v = v * sc[kk] + sh[kk];
            if (leaky) v = (v > 0.f) ? v : 0.1f * v;
            Ast[0][kk * 33 + r] = v;
        }
#pragma unroll
        for (int l = 0; l < 2; l++) {
            int i = tid + l * 256;
            int kk = i >> 4, c4 = i & 15;
            *reinterpret_cast<float4*>(&Bs[0][kk * 64 + c4 * 4]) =
                *reinterpret_cast<const float4*>(&W[(size_t)kk * N + col0 + c4 * 4]);
        }
    }
    __syncthreads();

    int cur = 0;
    for (int k0 = 0; k0 < K; k0 += 32) {
        int nxt = cur ^ 1;
        if (k0 + 32 < K) {
#pragma unroll
            for (int l = 0; l < 4; l++) {
                int i = tid + l * 256;
                int kk = i & 31, r = i >> 5;
                int k = k0 + 32 + kk;
                float v = A[(size_t)(row0 + r) * K + k];
                v = v * sc[k] + sh[k];
                if (leaky) v = (v > 0.f) ? v : 0.1f * v;
                Ast[nxt][kk * 33 + r] = v;
            }
#pragma unroll
            for (int l = 0; l < 2; l++) {
                int i = tid + l * 256;
                int kk = i >> 4, c4 = i & 15;
                *reinterpret_cast<float4*>(&Bs[nxt][kk * 64 + c4 * 4]) =
                    *reinterpret_cast<const float4*>(&W[(size_t)(k0 + 32 + kk) * N + col0 + c4 * 4]);
            }
        }
#pragma unroll 8
        for (int kk = 0; kk < 32; kk++) {
            float a0 = Ast[cur][kk * 33 + ty * 2];
            float a1 = Ast[cur][kk * 33 + ty * 2 + 1];
            float4 bb = *reinterpret_cast<const float4*>(&Bs[cur][kk * 64 + tx * 4]);
            acc[0][0] += a0 * bb.x; acc[0][1] += a0 * bb.y;
            acc[0][2] += a0 * bb.z; acc[0][3] += a0 * bb.w;
            acc[1][0] += a1 * bb.x; acc[1][1] += a1 * bb.y;
            acc[1][2] += a1 * bb.z; acc[1][3] += a1 * bb.w;
        }
        __syncthreads();
        cur = nxt;
    }
#pragma unroll
    for (int i = 0; i < 2; i++) {
        int r = row0 + ty * 2 + i, c = col0 + tx * 4;
        float4 o;
        o.x = acc[i][0] + bias[c + 0];
        o.y = acc[i][1] + bias[c + 1];
        o.z = acc[i][2] + bias[c + 2];
        o.w = acc[i][3] + bias[c + 3];
        *reinterpret_cast<float4*>(&C[(size_t)r * N + c]) = o;
    }
}

// =====================================================================
// final: out[b][0..1] = leaky(bn2(Z2)) @ w3 + b3
// =====================================================================
__global__ void __launch_bounds__(256) final_kernel(
    const float* __restrict__ w3, const float* __restrict__ b3,
    float* __restrict__ out)
{
    int b = blockIdx.x, tid = threadIdx.x;
    int lane = tid & 31, w = tid >> 5;
    float v = g_Z2[b * 256 + tid] * g_sc2[tid] + g_sh2[tid];
    v = (v > 0.f) ? v : 0.1f * v;
    float a0 = v * w3[tid * 2 + 0];
    float a1 = v * w3[tid * 2 + 1];
#pragma unroll
    for (int o = 16; o > 0; o >>= 1) {
        a0 += __shfl_xor_sync(0xffffffffu, a0, o);
        a1 += __shfl_xor_sync(0xffffffffu, a1, o);
    }
    __shared__ float r0s[8], r1s[8];
    if (lane == 0) { r0s[w] = a0; r1s[w] = a1; }
    __syncthreads();
    if (tid == 0) {
        float s0 = 0.f, s1 = 0.f;
        for (int i = 0; i < 8; i++) { s0 += r0s[i]; s1 += r1s[i]; }
        out[b * 2 + 0] = s0 + b3[0];
        out[b * 2 + 1] = s1 + b3[1];
    }
}

// =====================================================================
extern "C" void kernel_launch(void* const* d_in, const int* in_sizes, int n_in,
                              void* d_out, int out_size)
{
    (void)in_sizes; (void)n_in; (void)out_size;
    const int*   uid   = (const int*)d_in[0];
    const int*   mid   = (const int*)d_in[1];
    const int*   cat   = (const int*)d_in[2];
    const int*   hmid  = (const int*)d_in[3];
    const int*   hcat  = (const int*)d_in[4];
    const int*   mask  = (const int*)d_in[5];
    const float* utab  = (const float*)d_in[6];
    const float* mtab  = (const float*)d_in[7];
    const float* ctab  = (const float*)d_in[8];
    const float* lw1   = (const float*)d_in[9];
    const float* lb1   = (const float*)d_in[10];
    const float* lw2   = (const float*)d_in[11];
    const float* lb2   = (const float*)d_in[12];
    const float* lw3   = (const float*)d_in[13];
    const float* lb3   = (const float*)d_in[14];
    const float* bn0g  = (const float*)d_in[15];
    const float* bn0b  = (const float*)d_in[16];
    const float* mw1   = (const float*)d_in[17];
    const float* mb1   = (const float*)d_in[18];
    const float* bn1g  = (const float*)d_in[19];
    const float* bn1b  = (const float*)d_in[20];
    const float* mw2   = (const float*)d_in[21];
    const float* mb2   = (const float*)d_in[22];
    const float* bn2g  = (const float*)d_in[23];
    const float* bn2b  = (const float*)d_in[24];
    const float* mw3   = (const float*)d_in[25];
    const float* mb3   = (const float*)d_in[26];
    float* out = (float*)d_out;

    static int attr_done = 0;
    if (!attr_done) {
        cudaFuncSetAttribute(fused_kernel, cudaFuncAttributeMaxDynamicSharedMemorySize,
                             FUSED_SMEM);
        attr_done = 1;
    }

    float *sc0, *sh0, *sc1, *sh1, *sc2, *sh2, *X, *Z1, *Z2;
    cudaGetSymbolAddress((void**)&sc0, g_sc0);
    cudaGetSymbolAddress((void**)&sh0, g_sh0);
    cudaGetSymbolAddress((void**)&sc1, g_sc1);
    cudaGetSymbolAddress((void**)&sh1, g_sh1);
    cudaGetSymbolAddress((void**)&sc2, g_sc2);
    cudaGetSymbolAddress((void**)&sh2, g_sh2);
    cudaGetSymbolAddress((void**)&X,  g_X);
    cudaGetSymbolAddress((void**)&Z1, g_Z1);
    cudaGetSymbolAddress((void**)&Z2, g_Z2);

    prep_imgs<<<128, 256>>>(lw1, lw2);
    prep_w1ac<<<64, 256>>>(lw1);

    fused_kernel<<<BB, FTH, FUSED_SMEM>>>(uid, mid, cat, hmid, hcat, mask,
                                          utab, mtab, ctab, lb1, lb2, lw3, lb3);

    stats_kernel<<<448 / 32, 1024>>>(X, BB, 448, bn0g, bn0b, sc0, sh0);
    gemm_bn32<<<dim3(512 / 64, BB / 32), 256>>>(X, mw1, mb1, sc0, sh0, 0, 448, 512, Z1);

    stats_kernel<<<512 / 32, 1024>>>(Z1, BB, 512, bn1g, bn1b, sc1, sh1);
    gemm_bn32<<<dim3(256 / 64, BB / 32), 256>>>(Z1, mw2, mb2, sc1, sh1, 1, 512, 256, Z2);

    stats_kernel<<<256 / 32, 1024>>>(Z2, BB, 256, bn2g, bn2b, sc2, sh2);
    final_kernel<<<BB, 256>>>(mw3, mb3, out);
}

// round 16
// speedup vs baseline: 4.5337x; 1.1151x over previous
#include <cuda_runtime.h>
#include <cuda_fp16.h>
#include <math.h>
#include <stdint.h>

#define BB 1024
#define TT 200
#define EE 64

// ---------------- scratch (__device__ globals: allocation-free) ----------------
__device__ float g_X [BB * 448];
__device__ float g_Z1[BB * 512];
__device__ float g_Z2[BB * 256];
__device__ float g_sc0[448], g_sh0[448];
__device__ float g_sc1[512], g_sh1[512];
__device__ float g_sc2[256], g_sh2[256];
// column-stat accumulators: [0,448)=X, [448,960)=Z1, [960,1216)=Z2
__device__ float g_cs[1216], g_cq[1216];
// fp16 operand images, plain [n][k] row-major packed as half2 along k
__device__ unsigned g_imgBbc[16384];   // (W1b - W1c)^T  [256][64 half2]
__device__ unsigned g_imgBd [16384];   // (W1d)^T        [256][64 half2]
__device__ unsigned g_imgW2T[16384];   // W2^T           [128][128 half2]
__device__ unsigned g_W1ach[128 * 128]; // W1a + W1c, [k][j] as half2 pairs along j

__device__ __forceinline__ float sigm(float x) { return 1.0f / (1.0f + __expf(-x)); }

__device__ __forceinline__ unsigned pack2(float a, float b) {
    __half2 h = __floats2half2_rn(a, b);
    return *reinterpret_cast<unsigned*>(&h);
}
__device__ __forceinline__ unsigned hfma2u(unsigned c2, unsigned d2, unsigned b2v) {
    __half2 r = __hfma2(*reinterpret_cast<__half2*>(&c2),
                        *reinterpret_cast<__half2*>(&d2),
                        *reinterpret_cast<__half2*>(&b2v));
    return *reinterpret_cast<unsigned*>(&r);
}

// warp-level HMMA: D(16x8,f32) += A(16x16,f16 row) * B(16x8,f16 col)
__device__ __forceinline__ void mma16816(float* d, const unsigned* a,
                                         unsigned b0, unsigned b1) {
    asm volatile(
        "mma.sync.aligned.m16n8k16.row.col.f32.f16.f16.f32 "
        "{%0,%1,%2,%3}, {%4,%5,%6,%7}, {%8,%9}, {%0,%1,%2,%3};"
        : "+f"(d[0]), "+f"(d[1]), "+f"(d[2]), "+f"(d[3])
        : "r"(a[0]), "r"(a[1]), "r"(a[2]), "r"(a[3]), "r"(b0), "r"(b1));
}

// =====================================================================
// prep kernels: b-invariant fp16 operand images + zero stat accumulators
// =====================================================================
__global__ void __launch_bounds__(256) prep_imgs(const float* __restrict__ w1,
                                                 const float* __restrict__ w2)
{
    int gid = blockIdx.x * 256 + threadIdx.x;
    if (gid < 16384) {
        int j = gid >> 6, kk = gid & 63, k = kk * 2;
        float bc0 = w1[(128 + k) * 256 + j] - w1[(256 + k) * 256 + j];
        float bc1 = w1[(129 + k) * 256 + j] - w1[(257 + k) * 256 + j];
        g_imgBbc[gid] = pack2(bc0, bc1);
        g_imgBd [gid] = pack2(w1[(384 + k) * 256 + j], w1[(385 + k) * 256 + j]);
    } else {
        int t = gid - 16384;
        int j = t >> 7, kk = t & 127, k = kk * 2;
        g_imgW2T[t] = pack2(w2[k * 128 + j], w2[(k + 1) * 128 + j]);
    }
}

__global__ void __launch_bounds__(256) prep_w1ac(const float* __restrict__ w1)
{
    int gid = blockIdx.x * 256 + threadIdx.x;   // 16384 half2 elems, [k][j2]
    int k = gid >> 7, j = (gid & 127) * 2;
    float a = w1[k * 256 + j]     + w1[(256 + k) * 256 + j];
    float b = w1[k * 256 + j + 1] + w1[(256 + k) * 256 + j + 1];
    g_W1ach[gid] = pack2(a, b);
    if (gid < 1216) { g_cs[gid] = 0.f; g_cq[gid] = 0.f; }
}

// =====================================================================
// finalize: sums -> per-column affine
// =====================================================================
__global__ void __launch_bounds__(256) finalize_stats(
    int cols, const float* __restrict__ cs, const float* __restrict__ cq,
    const float* __restrict__ g, const float* __restrict__ bta,
    float* __restrict__ sc, float* __restrict__ sh)
{
    int i = blockIdx.x * 256 + threadIdx.x;
    if (i >= cols) return;
    float inv = 1.0f / (float)BB;
    float mu = cs[i] * inv;
    float var = cq[i] * inv - mu * mu;
    float scv = g[i] * rsqrtf(var + 1e-5f);
    sc[i] = scv;
    sh[i] = bta[i] - mu * scv;
}

// =====================================================================
// FUSED per-b kernel (512 threads, 16 warps)
// smem layout unchanged from R13 (see offsets)
// =====================================================================
#define LDA1 136
#define LDB1 136
#define LD2  264
#define OFF_A2 0
#define OFF_B  105600
#define OFF_A1 175232
#define OFF_C1 229632
#define OFF_CH 230656
#define FUSED_SMEM 231936
#define FTH 512

__global__ void __launch_bounds__(FTH) fused_kernel(
    const int* __restrict__ uid, const int* __restrict__ mid,
    const int* __restrict__ catid,
    const int* __restrict__ hmid, const int* __restrict__ hcat,
    const int* __restrict__ mask,
    const float* __restrict__ user_table, const float* __restrict__ mat_table,
    const float* __restrict__ cat_table,
    const float* __restrict__ b1, const float* __restrict__ b2,
    const float* __restrict__ w3, const float* __restrict__ b3)
{
    extern __shared__ __align__(16) char sm[];
    __half* A2 = reinterpret_cast<__half*>(sm + OFF_A2);
    __half* Bw = reinterpret_cast<__half*>(sm + OFF_B);
    __half* A1 = reinterpret_cast<__half*>(sm + OFF_A1);
    float*  c1s = reinterpret_cast<float*>(sm + OFF_C1);
    unsigned* curs2h = reinterpret_cast<unsigned*>(sm + OFF_CH);
    // misc overlay (valid only after GEMM1 + sync)
    float* s_aw  = reinterpret_cast<float*>(sm + OFF_A1);
    float* s_w3  = reinterpret_cast<float*>(sm + OFF_A1 + 832);
    float* s_b2  = reinterpret_cast<float*>(sm + OFF_A1 + 1344);
    float* s_lau = reinterpret_cast<float*>(sm + OFF_A1 + 1856);
    float* s_hs  = reinterpret_cast<float*>(sm + OFF_A1 + 2368);
    float* s_red = reinterpret_cast<float*>(sm + OFF_A1 + 2880);
    float* s_scal= reinterpret_cast<float*>(sm + OFF_A1 + 3008); // max,sum,cnt

    const int b = blockIdx.x, tid = threadIdx.x;
    const int wid = tid >> 5, lane = tid & 31;
    const int g = lane >> 2, t4 = lane & 3;

    // ---- prologue: cur as half2 ----
    if (tid < 64) {
        int c0 = 2 * tid;
        float v0 = (c0 < 64) ? mat_table[(size_t)mid[b] * EE + c0]
                             : cat_table[(size_t)catid[b] * EE + c0 - 64];
        float v1 = (c0 + 1 < 64) ? mat_table[(size_t)mid[b] * EE + c0 + 1]
                                 : cat_table[(size_t)catid[b] * EE + c0 + 1 - 64];
        curs2h[tid] = pack2(v0, v1);
    }
    __syncthreads();

    // ---- c1 (warps 0-3) ----
    if (tid < 128) {
        const int j2 = tid;
        float acc0 = b1[2 * j2], acc1 = b1[2 * j2 + 1];
#pragma unroll 8
        for (int kk = 0; kk < 64; kk++) {
            unsigned cu = curs2h[kk];
            __half2 c2 = *reinterpret_cast<__half2*>(&cu);
            float clo = __low2float(c2), chi = __high2float(c2);
            unsigned w0 = g_W1ach[(2 * kk) * 128 + j2];
            unsigned w1v = g_W1ach[(2 * kk + 1) * 128 + j2];
            __half2 h0 = *reinterpret_cast<__half2*>(&w0);
            __half2 h1 = *reinterpret_cast<__half2*>(&w1v);
            acc0 += clo * __low2float(h0)  + chi * __low2float(h1);
            acc1 += clo * __high2float(h0) + chi * __high2float(h1);
        }
        c1s[2 * j2] = acc0;
        c1s[2 * j2 + 1] = acc1;
    }
    // ---- Weff^T [256][128] fp16 into B region ----
    {
        unsigned ch = curs2h[tid & 63];
        for (int t = tid; t < 16384; t += FTH) {
            int j = t >> 6, kk = t & 63;
            *reinterpret_cast<unsigned*>(&Bw[j * LDB1 + kk * 2]) =
                hfma2u(ch, g_imgBd[t], g_imgBbc[t]);
        }
    }
    // ---- A1 = hist fp16, 200 rows ----
    for (int t = tid; t < 3200; t += FTH) {
        int r = t >> 4, kg = t & 15;
        const float* src = (kg < 8)
            ? (mat_table + (size_t)hmid[b * TT + r] * EE + kg * 8)
            : (cat_table + (size_t)hcat[b * TT + r] * EE + (kg - 8) * 8);
        float4 f0 = *reinterpret_cast<const float4*>(src);
        float4 f1 = *reinterpret_cast<const float4*>(src + 4);
        uint4 o;
        o.x = pack2(f0.x, f0.y); o.y = pack2(f0.z, f0.w);
        o.z = pack2(f1.x, f1.y); o.w = pack2(f1.z, f1.w);
        *reinterpret_cast<uint4*>(&A1[r * LDA1 + kg * 8]) = o;
    }
    __syncthreads();

    // ---- GEMM1: warp owns n-strip (32 cols), chunks of <=4 m-tiles,
    //      B fragments loaded once per k-step and reused across m ----
    {
        const int s = wid >> 1;                 // n-strip 0..7
        const int h = wid & 1;
        const int mstart = h ? 7 : 0;
        const int mcount = h ? 6 : 7;
        for (int cbase = 0; cbase < mcount; cbase += 4) {
            const int M = (mcount - cbase < 4) ? (mcount - cbase) : 4;
            float d[4][4][4];
#pragma unroll
            for (int mi = 0; mi < 4; mi++)
                for (int n8 = 0; n8 < 4; n8++)
                    { d[mi][n8][0]=0.f; d[mi][n8][1]=0.f; d[mi][n8][2]=0.f; d[mi][n8][3]=0.f; }
#pragma unroll 1
            for (int k0 = 0; k0 < 128; k0 += 16) {
                unsigned bb0[4], bb1[4];
#pragma unroll
                for (int n8 = 0; n8 < 4; n8++) {
                    int nr = s * 32 + n8 * 8 + g;
                    bb0[n8] = *reinterpret_cast<const unsigned*>(&Bw[nr * LDB1 + k0 + t4 * 2]);
                    bb1[n8] = *reinterpret_cast<const unsigned*>(&Bw[nr * LDB1 + k0 + 8 + t4 * 2]);
                }
#pragma unroll
                for (int mi = 0; mi < 4; mi++) {
                    if (mi < M) {
                        int m0 = (mstart + cbase + mi) * 16;
                        unsigned av[4];
                        av[0] = *reinterpret_cast<const unsigned*>(&A1[(m0 + g)     * LDA1 + k0 + t4 * 2]);
                        av[1] = *reinterpret_cast<const unsigned*>(&A1[(m0 + g + 8) * LDA1 + k0 + t4 * 2]);
                        av[2] = *reinterpret_cast<const unsigned*>(&A1[(m0 + g)     * LDA1 + k0 + 8 + t4 * 2]);
                        av[3] = *reinterpret_cast<const unsigned*>(&A1[(m0 + g + 8) * LDA1 + k0 + 8 + t4 * 2]);
#pragma unroll
                        for (int n8 = 0; n8 < 4; n8++)
                            mma16816(d[mi][n8], av, bb0[n8], bb1[n8]);
                    }
                }
            }
#pragma unroll
            for (int mi = 0; mi < 4; mi++) {
                if (mi < M) {
                    int m0 = (mstart + cbase + mi) * 16;
                    int r0 = m0 + g, r1 = m0 + g + 8;
#pragma unroll
                    for (int n8 = 0; n8 < 4; n8++) {
                        int col = s * 32 + n8 * 8 + t4 * 2;
                        *reinterpret_cast<unsigned*>(&A2[r0 * LD2 + col]) =
                            pack2(sigm(d[mi][n8][0] + c1s[col]), sigm(d[mi][n8][1] + c1s[col + 1]));
                        if (r1 < TT)
                            *reinterpret_cast<unsigned*>(&A2[r1 * LD2 + col]) =
                                pack2(sigm(d[mi][n8][2] + c1s[col]), sigm(d[mi][n8][3] + c1s[col + 1]));
                    }
                }
            }
        }
    }
    __syncthreads();

    // ---- phase B setup: W2T into B region (A1 region becomes misc) ----
    for (int t = tid; t < 16384; t += FTH) {
        int j = t >> 7, kk = t & 127;
        *reinterpret_cast<unsigned*>(&Bw[j * LD2 + kk * 2]) = g_imgW2T[t];
    }
    float b3v = b3[0];
    if (tid < 128) {
        s_w3[tid] = w3[tid];
        s_b2[tid] = b2[tid];
        s_lau[tid] = 0.f;
        s_hs[tid] = 0.f;
    }
    if (tid < 208) s_aw[tid] = b3v;
    __syncthreads();

    // ---- GEMM2: warp owns n-strip (32 cols), <=4 m-tiles, B reused ----
    {
        const int s = wid >> 2;                 // n-strip 0..3
        const int q = wid & 3;                  // m tiles: q, q+4, q+8 (+12 if q==0)
        const int M = (q == 0) ? 4 : 3;
        float d[4][4][4];
#pragma unroll
        for (int mi = 0; mi < 4; mi++)
            for (int n8 = 0; n8 < 4; n8++)
                { d[mi][n8][0]=0.f; d[mi][n8][1]=0.f; d[mi][n8][2]=0.f; d[mi][n8][3]=0.f; }
#pragma unroll 1
        for (int k0 = 0; k0 < 256; k0 += 16) {
            unsigned bb0[4], bb1[4];
#pragma unroll
            for (int n8 = 0; n8 < 4; n8++) {
                int nr = s * 32 + n8 * 8 + g;
                bb0[n8] = *reinterpret_cast<const unsigned*>(&Bw[nr * LD2 + k0 + t4 * 2]);
                bb1[n8] = *reinterpret_cast<const unsigned*>(&Bw[nr * LD2 + k0 + 8 + t4 * 2]);
            }
#pragma unroll
            for (int mi = 0; mi < 4; mi++) {
                if (mi < M) {
                    int m0 = (q + mi * 4) * 16;
                    unsigned av[4];
                    av[0] = *reinterpret_cast<const unsigned*>(&A2[(m0 + g)     * LD2 + k0 + t4 * 2]);
                    av[1] = *reinterpret_cast<const unsigned*>(&A2[(m0 + g + 8) * LD2 + k0 + t4 * 2]);
                    av[2] = *reinterpret_cast<const unsigned*>(&A2[(m0 + g)     * LD2 + k0 + 8 + t4 * 2]);
                    av[3] = *reinterpret_cast<const unsigned*>(&A2[(m0 + g + 8) * LD2 + k0 + 8 + t4 * 2]);
#pragma unroll
                    for (int n8 = 0; n8 < 4; n8++)
                        mma16816(d[mi][n8], av, bb0[n8], bb1[n8]);
                }
            }
        }
#pragma unroll
        for (int mi = 0; mi < 4; mi++) {
            if (mi < M) {
                int m0 = (q + mi * 4) * 16;
                float p0 = 0.f, p1 = 0.f;
#pragma unroll
                for (int n8 = 0; n8 < 4; n8++) {
                    int c = s * 32 + n8 * 8 + t4 * 2;
                    p0 += sigm(d[mi][n8][0] + s_b2[c]) * s_w3[c]
                        + sigm(d[mi][n8][1] + s_b2[c + 1]) * s_w3[c + 1];
                    p1 += sigm(d[mi][n8][2] + s_b2[c]) * s_w3[c]
                        + sigm(d[mi][n8][3] + s_b2[c + 1]) * s_w3[c + 1];
                }
                p0 += __shfl_xor_sync(0xffffffffu, p0, 1);
                p0 += __shfl_xor_sync(0xffffffffu, p0, 2);
                p1 += __shfl_xor_sync(0xffffffffu, p1, 1);
                p1 += __shfl_xor_sync(0xffffffffu, p1, 2);
                if (t4 == 0) {
                    atomicAdd(&s_aw[m0 + g], p0);
                    if (m0 + g + 8 < TT) atomicAdd(&s_aw[m0 + g + 8], p1);
                }
            }
        }
    }
    __syncthreads();

    // ---- masked softmax over t ----
    int mk = (tid < TT) ? mask[b * TT + tid] : 0;
    {
        float v = -3.0e38f;
        if (tid < TT && mk) v = s_aw[tid];
#pragma unroll
        for (int o = 16; o > 0; o >>= 1)
            v = fmaxf(v, __shfl_xor_sync(0xffffffffu, v, o));
        if (lane == 0) s_red[wid] = v;
        __syncthreads();
        if (tid == 0) {
            float m = s_red[0];
            for (int i = 1; i < 16; i++) m = fmaxf(m, s_red[i]);
            s_scal[0] = m;
        }
        __syncthreads();

        float e = 0.f, cf = 0.f;
        if (tid < TT && mk) { e = __expf(s_aw[tid] - s_scal[0]); cf = 1.f; }
        float se = e, scf = cf;
#pragma unroll
        for (int o = 16; o > 0; o >>= 1) {
            se  += __shfl_xor_sync(0xffffffffu, se, o);
            scf += __shfl_xor_sync(0xffffffffu, scf, o);
        }
        if (lane == 0) { s_red[wid] = se; s_red[16 + wid] = scf; }
        __syncthreads();
        if (tid == 0) {
            float ss = 0.f, cc = 0.f;
            for (int i = 0; i < 16; i++) { ss += s_red[i]; cc += s_red[16 + i]; }
            s_scal[1] = ss; s_scal[2] = cc;
        }
        __syncthreads();
        if (tid < TT) s_aw[tid] = e / s_scal[1];
        __syncthreads();
    }

    // ---- lau + masked sum over history (4 t-slices per column) ----
    {
        int col = tid & 127, quarter = tid >> 7;
        const float* tab = (col < 64) ? mat_table : cat_table;
        const int* hidx = (col < 64) ? hmid : hcat;
        int coff = (col < 64) ? col : (col - 64);
        float al = 0.f, ah = 0.f;
        for (int t2 = quarter; t2 < TT; t2 += 4) {
            int row = hidx[b * TT + t2];
            float h = tab[(size_t)row * EE + coff];
            al += s_aw[t2] * h;
            ah += (float)mask[b * TT + t2] * h;
        }
        atomicAdd(&s_lau[col], al);
        atomicAdd(&s_hs[col], ah);
    }
    __syncthreads();

    // ---- write X row + accumulate column stats for BN0 ----
    if (tid < 448) {
        float inv = 1.0f / s_scal[2];
        int i = tid;
        float v;
        if (i < 64)       v = user_table[(size_t)uid[b] * EE + i];
        else if (i < 192) {
            int c = i - 64;
            v = (c < 64) ? mat_table[(size_t)mid[b] * EE + c]
                         : cat_table[(size_t)catid[b] * EE + c - 64];
        }
        else if (i < 320) v = s_lau[i - 192];
        else              v = s_hs[i - 320] * inv;
        g_X[b * 448 + i] = v;
        atomicAdd(&g_cs[i], v);
        atomicAdd(&g_cq[i], v * v);
    }
}

// =====================================================================
// gemm_bn32: C[1024xN] = f(A) @ W + bias; 32x64 tile, double-buffered;
// accumulates per-column sum/sumsq of C into cs/cq (for next BN)
// =====================================================================
__global__ void __launch_bounds__(256) gemm_bn32(
    const float* __restrict__ A, const float* __restrict__ W,
    const float* __restrict__ bias, const float* __restrict__ sc,
    const float* __restrict__ sh, int leaky, int K, int N,
    float* __restrict__ C, float* __restrict__ cs, float* __restrict__ cq)
{
    __shared__ __align__(16) float Ast[2][32 * 33];
    __shared__ __align__(16) float Bs[2][32 * 64];
    __shared__ float colS[64], colQ[64];
    int tid = threadIdx.x;
    int row0 = blockIdx.y * 32, col0 = blockIdx.x * 64;
    int ty = tid >> 4, tx = tid & 15;
    float acc[2][4];
#pragma unroll
    for (int i = 0; i < 2; i++)
        for (int j = 0; j < 4; j++) acc[i][j] = 0.f;
    if (tid < 64) { colS[tid] = 0.f; colQ[tid] = 0.f; }

    {
#pragma unroll
        for (int l = 0; l < 4; l++) {
            int i = tid + l * 256;
            int kk = i & 31, r = i >> 5;
            float v = A[(size_t)(row0 + r) * K + kk];
            v = v * sc[kk] + sh[kk];
            if (leaky) v = (v > 0.f) ? v : 0.1f * v;
            Ast[0][kk * 33 + r] = v;
        }
#pragma unroll
        for (int l = 0; l < 2; l++) {
            int i = tid + l * 256;
            int kk = i >> 4, c4 = i & 15;
            *reinterpret_cast<float4*>(&Bs[0][kk * 64 + c4 * 4]) =
                *reinterpret_cast<const float4*>(&W[(size_t)kk * N + col0 + c4 * 4]);
        }
    }
    __syncthreads();

    int cur = 0;
    for (int k0 = 0; k0 < K; k0 += 32) {
        int nxt = cur ^ 1;
        if (k0 + 32 < K) {
#pragma unroll
            for (int l = 0; l < 4; l++) {
                int i = tid + l * 256;
                int kk = i & 31, r = i >> 5;
                int k = k0 + 32 + kk;
                float v = A[(size_t)(row0 + r) * K + k];
                v = v * sc[k] + sh[k];
                if (leaky) v = (v > 0.f) ? v : 0.1f * v;
                Ast[nxt][kk * 33 + r] = v;
            }
#pragma unroll
            for (int l = 0; l < 2; l++) {
                int i = tid + l * 256;
                int kk = i >> 4, c4 = i & 15;
                *reinterpret_cast<float4*>(&Bs[nxt][kk * 64 + c4 * 4]) =
                    *reinterpret_cast<const float4*>(&W[(size_t)(k0 + 32 + kk) * N + col0 + c4 * 4]);
            }
        }
#pragma unroll 8
        for (int kk = 0; kk < 32; kk++) {
            float a0 = Ast[cur][kk * 33 + ty * 2];
            float a1 = Ast[cur][kk * 33 + ty * 2 + 1];
            float4 bb = *reinterpret_cast<const float4*>(&Bs[cur][kk * 64 + tx * 4]);
            acc[0][0] += a0 * bb.x; acc[0][1] += a0 * bb.y;
            acc[0][2] += a0 * bb.z; acc[0][3] += a0 * bb.w;
            acc[1][0] += a1 * bb.x; acc[1][1] += a1 * bb.y;
            acc[1][2] += a1 * bb.z; acc[1][3] += a1 * bb.w;
        }
        __syncthreads();
        cur = nxt;
    }
    float o[2][4];
#pragma unroll
    for (int i = 0; i < 2; i++) {
        int r = row0 + ty * 2 + i, c = col0 + tx * 4;
        o[i][0] = acc[i][0] + bias[c + 0];
        o[i][1] = acc[i][1] + bias[c + 1];
        o[i][2] = acc[i][2] + bias[c + 2];
        o[i][3] = acc[i][3] + bias[c + 3];
        float4 ov = make_float4(o[i][0], o[i][1], o[i][2], o[i][3]);
        *reinterpret_cast<float4*>(&C[(size_t)r * N + c]) = ov;
    }
#pragma unroll
    for (int j = 0; j < 4; j++) {
        float sv = o[0][j] + o[1][j];
        float qv = o[0][j] * o[0][j] + o[1][j] * o[1][j];
        atomicAdd(&colS[tx * 4 + j], sv);
        atomicAdd(&colQ[tx * 4 + j], qv);
    }
    __syncthreads();
    if (tid < 64) {
        atomicAdd(&cs[col0 + tid], colS[tid]);
        atomicAdd(&cq[col0 + tid], colQ[tid]);
    }
}

// =====================================================================
// final: out[b][0..1] = leaky(bn2(Z2)) @ w3 + b3
// =====================================================================
__global__ void __launch_bounds__(256) final_kernel(
    const float* __restrict__ w3, const float* __restrict__ b3,
    float* __restrict__ out)
{
    int b = blockIdx.x, tid = threadIdx.x;
    int lane = tid & 31, w = tid >> 5;
    float v = g_Z2[b * 256 + tid] * g_sc2[tid] + g_sh2[tid];
    v = (v > 0.f) ? v : 0.1f * v;
    float a0 = v * w3[tid * 2 + 0];
    float a1 = v * w3[tid * 2 + 1];
#pragma unroll
    for (int o = 16; o > 0; o >>= 1) {
        a0 += __shfl_xor_sync(0xffffffffu, a0, o);
        a1 += __shfl_xor_sync(0xffffffffu, a1, o);
    }
    __shared__ float r0s[8], r1s[8];
    if (lane == 0) { r0s[w] = a0; r1s[w] = a1; }
    __syncthreads();
    if (tid == 0) {
        float s0 = 0.f, s1 = 0.f;
        for (int i = 0; i < 8; i++) { s0 += r0s[i]; s1 += r1s[i]; }
        out[b * 2 + 0] = s0 + b3[0];
        out[b * 2 + 1] = s1 + b3[1];
    }
}

// =====================================================================
extern "C" void kernel_launch(void* const* d_in, const int* in_sizes, int n_in,
                              void* d_out, int out_size)
{
    (void)in_sizes; (void)n_in; (void)out_size;
    const int*   uid   = (const int*)d_in[0];
    const int*   mid   = (const int*)d_in[1];
    const int*   cat   = (const int*)d_in[2];
    const int*   hmid  = (const int*)d_in[3];
    const int*   hcat  = (const int*)d_in[4];
    const int*   mask  = (const int*)d_in[5];
    const float* utab  = (const float*)d_in[6];
    const float* mtab  = (const float*)d_in[7];
    const float* ctab  = (const float*)d_in[8];
    const float* lw1   = (const float*)d_in[9];
    const float* lb1   = (const float*)d_in[10];
    const float* lw2   = (const float*)d_in[11];
    const float* lb2   = (const float*)d_in[12];
    const float* lw3   = (const float*)d_in[13];
    const float* lb3   = (const float*)d_in[14];
    const float* bn0g  = (const float*)d_in[15];
    const float* bn0b  = (const float*)d_in[16];
    const float* mw1   = (const float*)d_in[17];
    const float* mb1   = (const float*)d_in[18];
    const float* bn1g  = (const float*)d_in[19];
    const float* bn1b  = (const float*)d_in[20];
    const float* mw2   = (const float*)d_in[21];
    const float* mb2   = (const float*)d_in[22];
    const float* bn2g  = (const float*)d_in[23];
    const float* bn2b  = (const float*)d_in[24];
    const float* mw3   = (const float*)d_in[25];
    const float* mb3   = (const float*)d_in[26];
    float* out = (float*)d_out;

    static int attr_done = 0;
    if (!attr_done) {
        cudaFuncSetAttribute(fused_kernel, cudaFuncAttributeMaxDynamicSharedMemorySize,
                             FUSED_SMEM);
        attr_done = 1;
    }

    float *sc0, *sh0, *sc1, *sh1, *sc2, *sh2, *X, *Z1, *Z2, *cs, *cq;
    cudaGetSymbolAddress((void**)&sc0, g_sc0);
    cudaGetSymbolAddress((void**)&sh0, g_sh0);
    cudaGetSymbolAddress((void**)&sc1, g_sc1);
    cudaGetSymbolAddress((void**)&sh1, g_sh1);
    cudaGetSymbolAddress((void**)&sc2, g_sc2);
    cudaGetSymbolAddress((void**)&sh2, g_sh2);
    cudaGetSymbolAddress((void**)&X,  g_X);
    cudaGetSymbolAddress((void**)&Z1, g_Z1);
    cudaGetSymbolAddress((void**)&Z2, g_Z2);
    cudaGetSymbolAddress((void**)&cs, g_cs);
    cudaGetSymbolAddress((void**)&cq, g_cq);

    prep_imgs<<<128, 256>>>(lw1, lw2);
    prep_w1ac<<<64, 256>>>(lw1);

    fused_kernel<<<BB, FTH, FUSED_SMEM>>>(uid, mid, cat, hmid, hcat, mask,
                                          utab, mtab, ctab, lb1, lb2, lw3, lb3);

    finalize_stats<<<2, 256>>>(448, cs, cq, bn0g, bn0b, sc0, sh0);
    gemm_bn32<<<dim3(512 / 64, BB / 32), 256>>>(X, mw1, mb1, sc0, sh0, 0, 448, 512,
                                                Z1, cs + 448, cq + 448);

    finalize_stats<<<2, 256>>>(512, cs + 448, cq + 448, bn1g, bn1b, sc1, sh1);
    gemm_bn32<<<dim3(256 / 64, BB / 32), 256>>>(Z1, mw2, mb2, sc1, sh1, 1, 512, 256,
                                                Z2, cs + 960, cq + 960);

    finalize_stats<<<1, 256>>>(256, cs + 960, cq + 960, bn2g, bn2b, sc2, sh2);
    final_kernel<<<BB, 256>>>(mw3, mb3, out);
}